// round 1
// baseline (speedup 1.0000x reference)
#include <cuda_runtime.h>
#include <cuda_bf16.h>
#include <cstdint>

#define NTOT 7200      // B*L = 16*450
#define CIN  768
#define MIDD 256
#define KTOT 8912

// softmax scale constants (mirror fp32 reference arithmetic)
#define CT (2.0f/0.07f)   // logits = -d/TEMP ; shifted = (2/TEMP)(dot - maxdot)
#define CE (2.0f/0.01f)

// ---------------- device scratch (static; no allocations allowed) -------------
__device__ float g_zn[NTOT*MIDD];
__device__ float g_en[KTOT*MIDD];
__device__ unsigned long long g_rowkey[NTOT];
__device__ float g_maxdot[NTOT];
__device__ float g_invSt[NTOT];
__device__ float g_invSe[NTOT];
__device__ int   g_idx[NTOT];
__device__ int   g_occ[KTOT];
__device__ float g_avgp[KTOT];
__device__ float g_acc[4];   // [0]=sum d_min, [1]=sum per-row (sum p*lp)

// ---------------- helpers ----------------------------------------------------
__device__ __forceinline__ float warpReduceSum(float v){
    #pragma unroll
    for(int o=16;o;o>>=1) v += __shfl_xor_sync(0xFFFFFFFFu, v, o);
    return v;
}
// monotone float -> sortable uint
__device__ __forceinline__ unsigned fsort(float f){
    unsigned u = __float_as_uint(f);
    return u ^ ((u >> 31) ? 0xFFFFFFFFu : 0x80000000u);
}

// ---------------- K0: init scratch -------------------------------------------
__global__ void init_k(){
    int i = blockIdx.x*256 + threadIdx.x;
    if(i < NTOT) g_rowkey[i] = 0ull;
    if(i < KTOT){ g_avgp[i] = 0.f; g_occ[i] = 0; }
    if(i < 4) g_acc[i] = 0.f;
}

// ---------------- K1: normalize embedding ------------------------------------
__global__ void norm_emb(const float* __restrict__ emb){
    int k = blockIdx.x, m = threadIdx.x;
    float v = emb[k*MIDD + m];
    float s = warpReduceSum(v*v);
    __shared__ float sm[8];
    if((m & 31) == 0) sm[m>>5] = s;
    __syncthreads();
    if(m == 0){
        float t = 0.f;
        #pragma unroll
        for(int i=0;i<8;i++) t += sm[i];
        sm[0] = 1.f / fmaxf(sqrtf(t), 1e-12f);
    }
    __syncthreads();
    g_en[k*MIDD + m] = v * sm[0];
}

// ---------------- K1b: down projection + L2 norm ------------------------------
// 12 rows/block, 256 threads (one output column each). 600 blocks.
__global__ __launch_bounds__(256) void down_norm(const float* __restrict__ x,
                                                 const float* __restrict__ W,
                                                 const float* __restrict__ b){
    __shared__ float xs[12*CIN];
    __shared__ float red[8];
    __shared__ float rn[12];
    int m = threadIdx.x;
    size_t base = (size_t)blockIdx.x * 12 * CIN;
    const float4* xsrc = (const float4*)(x + base);
    float4* xd = (float4*)xs;
    for(int i=m; i < 12*CIN/4; i += 256) xd[i] = xsrc[i];
    __syncthreads();

    float acc[12];
    float bm = b[m];
    #pragma unroll
    for(int r=0;r<12;r++) acc[r] = bm;
    for(int c=0;c<CIN;c++){
        float w = W[c*MIDD + m];
        #pragma unroll
        for(int r=0;r<12;r++) acc[r] += xs[r*CIN + c] * w;
    }
    // per-row norm
    for(int r=0;r<12;r++){
        float s = warpReduceSum(acc[r]*acc[r]);
        if((m & 31) == 0) red[m>>5] = s;
        __syncthreads();
        if(m == 0){
            float t = 0.f;
            #pragma unroll
            for(int i=0;i<8;i++) t += red[i];
            rn[r] = 1.f / fmaxf(sqrtf(t), 1e-12f);
        }
        __syncthreads();
    }
    #pragma unroll
    for(int r=0;r<12;r++)
        g_zn[(size_t)(blockIdx.x*12 + r)*MIDD + m] = acc[r] * rn[r];
}

// ---------------- K2: main GEMM dot = zn @ en^T, fused rowmax/argmax ----------
// 128x128 tile, 256 threads, 8x8 per thread, double-buffered smem.
__global__ __launch_bounds__(256) void gemm_dot(float* __restrict__ Cc){
    __shared__ float As[2][8][128];
    __shared__ float Bs[2][8][128];
    int tid = threadIdx.x;
    int tx = tid & 15, ty = tid >> 4;
    int rowBase = blockIdx.y * 128;
    int colBase = blockIdx.x * 128;
    int lr = tid >> 1;
    int lc = (tid & 1) * 4;
    int arow = rowBase + lr;
    int brow = colBase + lr;
    const float4 z4 = {0.f,0.f,0.f,0.f};

    float acc[8][8];
    #pragma unroll
    for(int i=0;i<8;i++)
        #pragma unroll
        for(int j=0;j<8;j++) acc[i][j] = 0.f;

    float4 av = (arow < NTOT) ? *(const float4*)(g_zn + (size_t)arow*MIDD + lc) : z4;
    float4 bv = (brow < KTOT) ? *(const float4*)(g_en + (size_t)brow*MIDD + lc) : z4;
    As[0][lc+0][lr]=av.x; As[0][lc+1][lr]=av.y; As[0][lc+2][lr]=av.z; As[0][lc+3][lr]=av.w;
    Bs[0][lc+0][lr]=bv.x; Bs[0][lc+1][lr]=bv.y; Bs[0][lc+2][lr]=bv.z; Bs[0][lc+3][lr]=bv.w;
    __syncthreads();

    int p = 0;
    for(int kt=8; kt<=MIDD; kt+=8){
        float4 na = z4, nb = z4;
        if(kt < MIDD){
            na = (arow < NTOT) ? *(const float4*)(g_zn + (size_t)arow*MIDD + kt + lc) : z4;
            nb = (brow < KTOT) ? *(const float4*)(g_en + (size_t)brow*MIDD + kt + lc) : z4;
        }
        #pragma unroll
        for(int kk=0;kk<8;kk++){
            float a[8], b[8];
            *(float4*)(a)   = *(const float4*)&As[p][kk][ty*8];
            *(float4*)(a+4) = *(const float4*)&As[p][kk][ty*8+4];
            *(float4*)(b)   = *(const float4*)&Bs[p][kk][tx*8];
            *(float4*)(b+4) = *(const float4*)&Bs[p][kk][tx*8+4];
            #pragma unroll
            for(int i=0;i<8;i++)
                #pragma unroll
                for(int j=0;j<8;j++) acc[i][j] += a[i]*b[j];
        }
        if(kt < MIDD){
            int q = p ^ 1;
            As[q][lc+0][lr]=na.x; As[q][lc+1][lr]=na.y; As[q][lc+2][lr]=na.z; As[q][lc+3][lr]=na.w;
            Bs[q][lc+0][lr]=nb.x; Bs[q][lc+1][lr]=nb.y; Bs[q][lc+2][lr]=nb.z; Bs[q][lc+3][lr]=nb.w;
            p = q;
            __syncthreads();
        }
    }

    // epilogue: store dots + fused per-row (max, argmax) -> packed u64 atomicMax
    #pragma unroll
    for(int i=0;i<8;i++){
        int row = rowBase + ty*8 + i;
        bool rok = row < NTOT;
        float best = -1e30f; int bcol = 0;
        float* crow = Cc + (size_t)row * KTOT;
        #pragma unroll
        for(int j=0;j<8;j++){
            int col = colBase + tx*8 + j;
            if(rok && col < KTOT){
                crow[col] = acc[i][j];
                if(acc[i][j] > best){ best = acc[i][j]; bcol = col; }
            }
        }
        unsigned long long key = rok
            ? (((unsigned long long)fsort(best)) << 32) | (unsigned long long)(0xFFFFFFFFu - (unsigned)bcol)
            : 0ull;
        #pragma unroll
        for(int off=8; off; off>>=1){
            unsigned long long o = __shfl_xor_sync(0xFFFFFFFFu, key, off);
            if(o > key) key = o;
        }
        if(tx == 0 && rok) atomicMax(&g_rowkey[row], key);
    }
}

// ---------------- K3: per-row softmax stats -----------------------------------
__global__ void row_stats(const float* __restrict__ Cc){
    int n = blockIdx.x, t = threadIdx.x;
    unsigned long long key = g_rowkey[n];
    unsigned u = (unsigned)(key >> 32);
    unsigned ub = (u & 0x80000000u) ? (u ^ 0x80000000u) : ~u;
    float md = __uint_as_float(ub);
    int idx = (int)(0xFFFFFFFFu - (unsigned)(key & 0xFFFFFFFFull));

    const float* row = Cc + (size_t)n * KTOT;
    float st = 0.f, se = 0.f, te = 0.f;
    for(int k=t; k<KTOT; k+=256){
        float g = row[k] - md;
        st += __expf(CT * g);
        float ge = CE * g;
        float e = __expf(ge);
        se += e;
        te += e * ge;
    }
    st = warpReduceSum(st); se = warpReduceSum(se); te = warpReduceSum(te);
    __shared__ float r0[8], r1[8], r2[8];
    if((t & 31) == 0){ r0[t>>5]=st; r1[t>>5]=se; r2[t>>5]=te; }
    __syncthreads();
    if(t == 0){
        float a=0.f, b=0.f, c=0.f;
        #pragma unroll
        for(int i=0;i<8;i++){ a+=r0[i]; b+=r1[i]; c+=r2[i]; }
        g_invSt[n] = 1.f / a;
        g_invSe[n] = 1.f / b;
        g_maxdot[n] = md;
        g_idx[n] = idx;
        g_occ[idx] = 1;
        atomicAdd(&g_acc[0], 2.f - 2.f*md);          // d_min
        atomicAdd(&g_acc[1], c/b - logf(b));         // per-row sum p*lp
    }
}

// ---------------- K4: write probs + column sums of ent-probs -------------------
// grid (ceil(K/256), 36); each y-chunk handles 200 rows; thread owns column k.
__global__ void probs_avg(float* __restrict__ Cc){
    int k = blockIdx.x*256 + threadIdx.x;
    bool ok = k < KTOT;
    int n0 = blockIdx.y * 200;
    float accp = 0.f;
    for(int n=n0; n<n0+200; n++){
        float md  = g_maxdot[n];
        float ist = g_invSt[n];
        float ise = g_invSe[n];
        if(ok){
            size_t off = (size_t)n * KTOT + k;
            float g = Cc[off] - md;
            Cc[off] = __expf(CT * g) * ist;
            accp   += __expf(CE * g) * ise;
        }
    }
    if(ok) atomicAdd(&g_avgp[k], accp);
}

// ---------------- K5: scalars --------------------------------------------------
__global__ void finalize(float* __restrict__ scal){
    int t = threadIdx.x;
    float cnt = 0.f, s = 0.f;
    for(int k=t; k<KTOT; k+=256){
        cnt += g_occ[k] ? 1.f : 0.f;
        float ap = g_avgp[k] * (1.f/7200.f);
        s += ap * logf(ap + 1e-5f);
    }
    cnt = warpReduceSum(cnt); s = warpReduceSum(s);
    __shared__ float r0[8], r1[8];
    if((t & 31) == 0){ r0[t>>5]=cnt; r1[t>>5]=s; }
    __syncthreads();
    if(t == 0){
        float c=0.f, sl=0.f;
        #pragma unroll
        for(int i=0;i<8;i++){ c+=r0[i]; sl+=r1[i]; }
        float usage = c / (float)KTOT;
        float vq = g_acc[0] / (7200.f * 256.f);
        float sample_entropy = -(g_acc[1] / 7200.f);
        float entropy_loss = sample_entropy + sl;   // sample - (-sl)
        scal[0] = usage;
        scal[1] = vq;
        scal[2] = vq;           // commit_loss is numerically identical
        scal[3] = entropy_loss;
    }
}

// ---------------- K6: gather z_q_ste = en[idx] --------------------------------
__global__ void gather_zq(float* __restrict__ outz){
    int n = blockIdx.x, m = threadIdx.x;
    outz[(size_t)n*MIDD + m] = g_en[(size_t)g_idx[n]*MIDD + m];
}

// ---------------- launch ------------------------------------------------------
extern "C" void kernel_launch(void* const* d_in, const int* in_sizes, int n_in,
                              void* d_out, int out_size){
    const float* x   = (const float*)d_in[0];
    const float* W   = (const float*)d_in[1];
    const float* b   = (const float*)d_in[2];
    const float* emb = (const float*)d_in[3];
    float* out = (float*)d_out;
    float* zq = out;
    float* probs = out + (size_t)NTOT*MIDD;
    float* scal  = out + (size_t)NTOT*MIDD + (size_t)NTOT*KTOT;

    init_k<<<(KTOT+255)/256, 256>>>();
    norm_emb<<<KTOT, 256>>>(emb);
    down_norm<<<NTOT/12, 256>>>(x, W, b);
    dim3 g2((KTOT+127)/128, (NTOT+127)/128);
    gemm_dot<<<g2, 256>>>(probs);
    row_stats<<<NTOT, 256>>>(probs);
    probs_avg<<<dim3((KTOT+255)/256, 36), 256>>>(probs);
    finalize<<<1, 256>>>(scal);
    gather_zq<<<NTOT, 256>>>(zq);
}

// round 3
// speedup vs baseline: 1.9018x; 1.9018x over previous
#include <cuda_runtime.h>
#include <cuda_bf16.h>
#include <cstdint>

#define NTOT 7200      // B*L
#define NPAD 7296      // 57 * 128
#define CIN  768
#define MIDD 256
#define KTOT 8912
#define KPAD 8960      // 70 * 128

#define CT (2.0f/0.07f)
#define CE (2.0f/0.01f)

// ------------- device scratch -------------
__device__ __nv_bfloat16 g_znh[NPAD*MIDD];
__device__ __nv_bfloat16 g_znl[NPAD*MIDD];
__device__ __nv_bfloat16 g_enh[KPAD*MIDD];
__device__ __nv_bfloat16 g_enl[KPAD*MIDD];
__device__ float g_en[KTOT*MIDD];
__device__ unsigned long long g_rowkey[NTOT];
__device__ float g_maxdot[NTOT];
__device__ float g_invSt[NTOT];
__device__ float g_invSe[NTOT];
__device__ int   g_idx[NTOT];
__device__ int   g_occ[KTOT];
__device__ float g_avgp[KTOT];
__device__ float g_acc[4];

// ------------- helpers -------------
__device__ __forceinline__ float warpReduceSum(float v){
    #pragma unroll
    for(int o=16;o;o>>=1) v += __shfl_xor_sync(0xFFFFFFFFu, v, o);
    return v;
}
__device__ __forceinline__ unsigned fsort(float f){
    unsigned u = __float_as_uint(f);
    return u ^ ((u >> 31) ? 0xFFFFFFFFu : 0x80000000u);
}
__device__ __forceinline__ uint32_t smem_u32(const void* p){
    uint32_t a;
    asm("{ .reg .u64 t; cvta.to.shared.u64 t, %1; cvt.u32.u64 %0, t; }" : "=r"(a) : "l"(p));
    return a;
}
__device__ __forceinline__ void cpa16(uint32_t s, const void* g){
    asm volatile("cp.async.cg.shared.global [%0], [%1], 16;" :: "r"(s), "l"(g));
}
#define LDSM4(R, ADDR) \
    asm volatile("ldmatrix.sync.aligned.m8n8.x4.shared.b16 {%0,%1,%2,%3}, [%4];" \
        : "=r"((R)[0]), "=r"((R)[1]), "=r"((R)[2]), "=r"((R)[3]) : "r"(ADDR))
#define MMA16816(D, A, B0, B1) \
    asm volatile("mma.sync.aligned.m16n8k16.row.col.f32.bf16.bf16.f32 " \
        "{%0,%1,%2,%3},{%4,%5,%6,%7},{%8,%9},{%0,%1,%2,%3};" \
        : "+f"((D)[0]), "+f"((D)[1]), "+f"((D)[2]), "+f"((D)[3]) \
        : "r"((A)[0]), "r"((A)[1]), "r"((A)[2]), "r"((A)[3]), "r"(B0), "r"(B1))

// ------------- K0: init -------------
__global__ void init_k(){
    int i = blockIdx.x*256 + threadIdx.x;
    if(i < NTOT) g_rowkey[i] = 0ull;
    if(i < KTOT){ g_avgp[i] = 0.f; g_occ[i] = 0; }
    if(i < 4) g_acc[i] = 0.f;
}

// ------------- K1: normalize embedding + bf16 split -------------
__global__ void norm_emb(const float* __restrict__ emb){
    int k = blockIdx.x, m = threadIdx.x;
    float v = emb[k*MIDD + m];
    float s = warpReduceSum(v*v);
    __shared__ float sm[8];
    if((m & 31) == 0) sm[m>>5] = s;
    __syncthreads();
    if(m == 0){
        float t = 0.f;
        #pragma unroll
        for(int i=0;i<8;i++) t += sm[i];
        sm[0] = 1.f / fmaxf(sqrtf(t), 1e-12f);
    }
    __syncthreads();
    float nv = v * sm[0];
    g_en[k*MIDD + m] = nv;
    __nv_bfloat16 h = __float2bfloat16(nv);
    g_enh[k*MIDD + m] = h;
    g_enl[k*MIDD + m] = __float2bfloat16(nv - __bfloat162float(h));
}

// ------------- K1b: down projection + L2 norm + bf16 split -------------
__global__ __launch_bounds__(256) void down_norm(const float* __restrict__ x,
                                                 const float* __restrict__ W,
                                                 const float* __restrict__ b){
    __shared__ float xs[12*CIN];
    __shared__ float red[8];
    __shared__ float rn[12];
    int m = threadIdx.x;
    size_t base = (size_t)blockIdx.x * 12 * CIN;
    const float4* xsrc = (const float4*)(x + base);
    float4* xd = (float4*)xs;
    for(int i=m; i < 12*CIN/4; i += 256) xd[i] = xsrc[i];
    __syncthreads();

    float acc[12];
    float bm = b[m];
    #pragma unroll
    for(int r=0;r<12;r++) acc[r] = bm;
    for(int c=0;c<CIN;c++){
        float w = W[c*MIDD + m];
        #pragma unroll
        for(int r=0;r<12;r++) acc[r] += xs[r*CIN + c] * w;
    }
    for(int r=0;r<12;r++){
        float s = warpReduceSum(acc[r]*acc[r]);
        if((m & 31) == 0) red[m>>5] = s;
        __syncthreads();
        if(m == 0){
            float t = 0.f;
            #pragma unroll
            for(int i=0;i<8;i++) t += red[i];
            rn[r] = 1.f / fmaxf(sqrtf(t), 1e-12f);
        }
        __syncthreads();
    }
    #pragma unroll
    for(int r=0;r<12;r++){
        size_t o = (size_t)(blockIdx.x*12 + r)*MIDD + m;
        float v = acc[r] * rn[r];
        __nv_bfloat16 h = __float2bfloat16(v);
        g_znh[o] = h;
        g_znl[o] = __float2bfloat16(v - __bfloat162float(h));
    }
}

// ------------- GEMM: mma.sync bf16 3-product split -------------
// Tile 128x128, BK=32, 8 warps (2x4), warp tile 64x32. Smem rows padded to
// 80B (stride 40 bf16) for conflict-free ldmatrix.
#define ROWB 80
__global__ __launch_bounds__(256) void gemm_mma(float* __restrict__ Cc){
    __shared__ __align__(16) char smA[2][128*ROWB];
    __shared__ __align__(16) char smB[2][128*ROWB];

    int t = threadIdx.x;
    int lane = t & 31, w = t >> 5;
    int rowBase = blockIdx.y * 128;
    int colBase = blockIdx.x * 128;

    // 3 passes over K=256: (ah,bh), (ah,bl), (al,bh)
    const __nv_bfloat16* Asrc[3] = {g_znh, g_znh, g_znl};
    const __nv_bfloat16* Bsrc[3] = {g_enh, g_enl, g_enh};

    // cp.async thread mapping: row = t>>1, two 16B units starting at (t&1)*2
    int ldr = t >> 1;
    int ldq = (t & 1) * 2;
    uint32_t sA0 = smem_u32(smA[0]) + ldr*ROWB + ldq*16;
    uint32_t sA1 = smem_u32(smA[1]) + ldr*ROWB + ldq*16;
    uint32_t sB0 = smem_u32(smB[0]) + ldr*ROWB + ldq*16;
    uint32_t sB1 = smem_u32(smB[1]) + ldr*ROWB + ldq*16;

    // ldmatrix per-lane offsets
    int wm = (w & 1) * 64, wn = (w >> 1) * 32;
    int arow = wm + ((lane >> 3) & 1) * 8 + (lane & 7);
    int acol = (lane >> 4) * 8;
    uint32_t aoff = arow*ROWB + acol*2;
    int brow = wn + (lane >> 4) * 8 + (lane & 7);
    int bcol = ((lane >> 3) & 1) * 8;
    uint32_t boff = brow*ROWB + bcol*2;
    uint32_t baseA[2] = { smem_u32(smA[0]) + aoff, smem_u32(smA[1]) + aoff };
    uint32_t baseB[2] = { smem_u32(smB[0]) + boff, smem_u32(smB[1]) + boff };

    float acc[4][4][4];
    #pragma unroll
    for(int i=0;i<4;i++)
        #pragma unroll
        for(int j=0;j<4;j++)
            #pragma unroll
            for(int q=0;q<4;q++) acc[i][j][q] = 0.f;

    // issue chunk c into buffer buf
    auto issue = [&](int c, int buf){
        int p = c >> 3;
        int ko = (c & 7) * 32;
        const __nv_bfloat16* As = Asrc[p] + (size_t)(rowBase + ldr)*MIDD + ko + ldq*8;
        const __nv_bfloat16* Bs = Bsrc[p] + (size_t)(colBase + ldr)*MIDD + ko + ldq*8;
        uint32_t sa = buf ? sA1 : sA0;
        uint32_t sb = buf ? sB1 : sB0;
        cpa16(sa,      As);
        cpa16(sa + 16, As + 8);
        cpa16(sb,      Bs);
        cpa16(sb + 16, Bs + 8);
    };

    issue(0, 0);
    asm volatile("cp.async.commit_group;");

    for(int c = 0; c < 24; c++){
        int buf = c & 1;
        if(c < 23){
            issue(c+1, buf ^ 1);
            asm volatile("cp.async.commit_group;");
            asm volatile("cp.async.wait_group 1;");
        } else {
            asm volatile("cp.async.wait_group 0;");
        }
        __syncthreads();

        #pragma unroll
        for(int s=0;s<2;s++){
            uint32_t Af[4][4];
            #pragma unroll
            for(int i=0;i<4;i++)
                LDSM4(Af[i], baseA[buf] + i*(16*ROWB) + s*32);
            uint32_t Bf[2][4];
            #pragma unroll
            for(int jp=0;jp<2;jp++)
                LDSM4(Bf[jp], baseB[buf] + jp*(16*ROWB) + s*32);
            #pragma unroll
            for(int i=0;i<4;i++)
                #pragma unroll
                for(int j=0;j<4;j++)
                    MMA16816(acc[i][j], Af[i], Bf[j>>1][(j&1)*2], Bf[j>>1][(j&1)*2+1]);
        }
        __syncthreads();
    }

    // epilogue: store dots + fused per-row argmax
    #pragma unroll
    for(int i=0;i<4;i++){
        int r0 = rowBase + wm + i*16 + (lane >> 2);
        #pragma unroll
        for(int h=0;h<2;h++){
            int row = r0 + h*8;
            bool rok = row < NTOT;
            float best = -3.0e38f; int bcol = 0;
            float* crow = Cc + (size_t)row * KTOT;
            #pragma unroll
            for(int j=0;j<4;j++){
                int col = colBase + wn + j*8 + (lane & 3)*2;
                float v0 = acc[i][j][h*2+0];
                float v1 = acc[i][j][h*2+1];
                if(rok && col < KTOT){
                    float2 v2 = {v0, v1};
                    *(float2*)(crow + col) = v2;
                    if(v0 > best){ best = v0; bcol = col; }
                    if(v1 > best){ best = v1; bcol = col+1; }
                }
            }
            unsigned long long key = rok
                ? (((unsigned long long)fsort(best)) << 32) |
                  (unsigned long long)(0xFFFFFFFFu - (unsigned)bcol)
                : 0ull;
            {
                unsigned long long o1 = __shfl_xor_sync(0xFFFFFFFFu, key, 1);
                if(o1 > key) key = o1;
                unsigned long long o2 = __shfl_xor_sync(0xFFFFFFFFu, key, 2);
                if(o2 > key) key = o2;
            }
            if((lane & 3) == 0 && rok) atomicMax(&g_rowkey[row], key);
        }
    }
}

// ------------- K3: per-row softmax stats -------------
__global__ void row_stats(const float* __restrict__ Cc){
    int n = blockIdx.x, t = threadIdx.x;
    unsigned long long key = g_rowkey[n];
    unsigned u = (unsigned)(key >> 32);
    unsigned ub = (u & 0x80000000u) ? (u ^ 0x80000000u) : ~u;
    float md = __uint_as_float(ub);
    int idx = (int)(0xFFFFFFFFu - (unsigned)(key & 0xFFFFFFFFull));

    const float* row = Cc + (size_t)n * KTOT;
    float st = 0.f, se = 0.f, te = 0.f;
    for(int k=t; k<KTOT; k+=256){
        float g = row[k] - md;
        st += __expf(CT * g);
        float ge = CE * g;
        float e = __expf(ge);
        se += e;
        te += e * ge;
    }
    st = warpReduceSum(st); se = warpReduceSum(se); te = warpReduceSum(te);
    __shared__ float r0[8], r1[8], r2[8];
    if((t & 31) == 0){ r0[t>>5]=st; r1[t>>5]=se; r2[t>>5]=te; }
    __syncthreads();
    if(t == 0){
        float a=0.f, b=0.f, c=0.f;
        #pragma unroll
        for(int i=0;i<8;i++){ a+=r0[i]; b+=r1[i]; c+=r2[i]; }
        g_invSt[n] = 1.f / a;
        g_invSe[n] = 1.f / b;
        g_maxdot[n] = md;
        g_idx[n] = idx;
        g_occ[idx] = 1;
        atomicAdd(&g_acc[0], 2.f - 2.f*md);
        atomicAdd(&g_acc[1], c/b - logf(b));
    }
}

// ------------- K4: write probs + entropy column sums -------------
__global__ void probs_avg(float* __restrict__ Cc){
    int k = blockIdx.x*256 + threadIdx.x;
    bool ok = k < KTOT;
    int n0 = blockIdx.y * 200;
    float accp = 0.f;
    for(int n=n0; n<n0+200; n++){
        float md  = g_maxdot[n];
        float ist = g_invSt[n];
        float ise = g_invSe[n];
        if(ok){
            size_t off = (size_t)n * KTOT + k;
            float g = Cc[off] - md;
            Cc[off] = __expf(CT * g) * ist;
            accp   += __expf(CE * g) * ise;
        }
    }
    if(ok) atomicAdd(&g_avgp[k], accp);
}

// ------------- K5: scalars -------------
__global__ void finalize(float* __restrict__ scal){
    int t = threadIdx.x;
    float cnt = 0.f, s = 0.f;
    for(int k=t; k<KTOT; k+=256){
        cnt += g_occ[k] ? 1.f : 0.f;
        float ap = g_avgp[k] * (1.f/7200.f);
        s += ap * logf(ap + 1e-5f);
    }
    cnt = warpReduceSum(cnt); s = warpReduceSum(s);
    __shared__ float r0[8], r1[8];
    if((t & 31) == 0){ r0[t>>5]=cnt; r1[t>>5]=s; }
    __syncthreads();
    if(t == 0){
        float c=0.f, sl=0.f;
        #pragma unroll
        for(int i=0;i<8;i++){ c+=r0[i]; sl+=r1[i]; }
        float usage = c / (float)KTOT;
        float vq = g_acc[0] / (7200.f * 256.f);
        float sample_entropy = -(g_acc[1] / 7200.f);
        scal[0] = usage;
        scal[1] = vq;
        scal[2] = vq;
        scal[3] = sample_entropy + sl;
    }
}

// ------------- K6: gather z_q_ste -------------
__global__ void gather_zq(float* __restrict__ outz){
    int n = blockIdx.x, m = threadIdx.x;
    outz[(size_t)n*MIDD + m] = g_en[(size_t)g_idx[n]*MIDD + m];
}

// ------------- launch -------------
extern "C" void kernel_launch(void* const* d_in, const int* in_sizes, int n_in,
                              void* d_out, int out_size){
    const float* x   = (const float*)d_in[0];
    const float* W   = (const float*)d_in[1];
    const float* b   = (const float*)d_in[2];
    const float* emb = (const float*)d_in[3];
    float* out = (float*)d_out;
    float* zq = out;
    float* probs = out + (size_t)NTOT*MIDD;
    float* scal  = out + (size_t)NTOT*MIDD + (size_t)NTOT*KTOT;

    init_k<<<(KTOT+255)/256, 256>>>();
    norm_emb<<<KTOT, 256>>>(emb);
    down_norm<<<NTOT/12, 256>>>(x, W, b);
    gemm_mma<<<dim3(KPAD/128, NPAD/128), 256>>>(probs);
    row_stats<<<NTOT, 256>>>(probs);
    probs_avg<<<dim3((KTOT+255)/256, 36), 256>>>(probs);
    finalize<<<1, 256>>>(scal);
    gather_zq<<<NTOT, 256>>>(zq);
}

// round 4
// speedup vs baseline: 2.1983x; 1.1559x over previous
#include <cuda_runtime.h>
#include <cuda_bf16.h>
#include <cstdint>

#define NTOT 7200      // B*L
#define NPAD 7296      // 57 * 128  (also 114 * 64)
#define CIN  768
#define MIDD 256
#define KTOT 8912
#define KPAD 8960      // 70 * 128
#define KV4  2228      // KTOT/4

#define CT (2.0f/0.07f)
#define CE (2.0f/0.01f)
#define ROWB 80

// ------------- device scratch -------------
__device__ __nv_bfloat16 g_znh[NPAD*MIDD];
__device__ __nv_bfloat16 g_znl[NPAD*MIDD];
__device__ __nv_bfloat16 g_enh[KPAD*MIDD];
__device__ __nv_bfloat16 g_enl[KPAD*MIDD];
__device__ __nv_bfloat16 g_xh[NPAD*CIN];   // zero-init tail rows stay zero
__device__ __nv_bfloat16 g_xl[NPAD*CIN];
__device__ __nv_bfloat16 g_wth[MIDD*CIN];  // W^T split
__device__ __nv_bfloat16 g_wtl[MIDD*CIN];
__device__ float g_en[KTOT*MIDD];
__device__ unsigned long long g_rowkey[NTOT];
__device__ float g_maxdot[NTOT];
__device__ float g_invSt[NTOT];
__device__ float g_invSe[NTOT];
__device__ int   g_idx[NTOT];
__device__ int   g_occ[KTOT];
__device__ float g_avgp[KTOT];
__device__ float g_acc[4];

// ------------- helpers -------------
__device__ __forceinline__ float warpReduceSum(float v){
    #pragma unroll
    for(int o=16;o;o>>=1) v += __shfl_xor_sync(0xFFFFFFFFu, v, o);
    return v;
}
__device__ __forceinline__ unsigned fsort(float f){
    unsigned u = __float_as_uint(f);
    return u ^ ((u >> 31) ? 0xFFFFFFFFu : 0x80000000u);
}
__device__ __forceinline__ uint32_t smem_u32(const void* p){
    uint32_t a;
    asm("{ .reg .u64 t; cvta.to.shared.u64 t, %1; cvt.u32.u64 %0, t; }" : "=r"(a) : "l"(p));
    return a;
}
__device__ __forceinline__ void cpa16(uint32_t s, const void* g){
    asm volatile("cp.async.cg.shared.global [%0], [%1], 16;" :: "r"(s), "l"(g));
}
__device__ __forceinline__ void cp_commit(){
    asm volatile("cp.async.commit_group;");
}
template<int N> __device__ __forceinline__ void cp_wait(){
    asm volatile("cp.async.wait_group %0;" :: "n"(N));
}
#define LDSM4(R, ADDR) \
    asm volatile("ldmatrix.sync.aligned.m8n8.x4.shared.b16 {%0,%1,%2,%3}, [%4];" \
        : "=r"((R)[0]), "=r"((R)[1]), "=r"((R)[2]), "=r"((R)[3]) : "r"(ADDR))
#define MMA16816(D, A, B0, B1) \
    asm volatile("mma.sync.aligned.m16n8k16.row.col.f32.bf16.bf16.f32 " \
        "{%0,%1,%2,%3},{%4,%5,%6,%7},{%8,%9},{%0,%1,%2,%3};" \
        : "+f"((D)[0]), "+f"((D)[1]), "+f"((D)[2]), "+f"((D)[3]) \
        : "r"((A)[0]), "r"((A)[1]), "r"((A)[2]), "r"((A)[3]), "r"(B0), "r"(B1))

__device__ __forceinline__ void bsplit(float v, __nv_bfloat16& h, __nv_bfloat16& l){
    h = __float2bfloat16(v);
    l = __float2bfloat16(v - __bfloat162float(h));
}

// ------------- K0: init -------------
__global__ void init_k(){
    int i = blockIdx.x*256 + threadIdx.x;
    if(i < NTOT) g_rowkey[i] = 0ull;
    if(i < KTOT){ g_avgp[i] = 0.f; g_occ[i] = 0; }
    if(i < 4) g_acc[i] = 0.f;
}

// ------------- K1: normalize embedding + bf16 split -------------
__global__ void norm_emb(const float* __restrict__ emb){
    int k = blockIdx.x, m = threadIdx.x;
    float v = emb[k*MIDD + m];
    float s = warpReduceSum(v*v);
    __shared__ float sm[8];
    if((m & 31) == 0) sm[m>>5] = s;
    __syncthreads();
    if(m == 0){
        float t = 0.f;
        #pragma unroll
        for(int i=0;i<8;i++) t += sm[i];
        sm[0] = 1.f / fmaxf(sqrtf(t), 1e-12f);
    }
    __syncthreads();
    float nv = v * sm[0];
    g_en[k*MIDD + m] = nv;
    __nv_bfloat16 h, l;
    bsplit(nv, h, l);
    g_enh[k*MIDD + m] = h;
    g_enl[k*MIDD + m] = l;
}

// ------------- K1a: split x into bf16 hi/lo -------------
__global__ void split_x(const float* __restrict__ x){
    int i = blockIdx.x*256 + threadIdx.x;    // float4 index
    if(i < NTOT*CIN/4){
        float4 v = ((const float4*)x)[i];
        __nv_bfloat16 h0,l0,h1,l1,h2,l2,h3,l3;
        bsplit(v.x,h0,l0); bsplit(v.y,h1,l1); bsplit(v.z,h2,l2); bsplit(v.w,h3,l3);
        __nv_bfloat162 ha; ha.x=h0; ha.y=h1;
        __nv_bfloat162 hb; hb.x=h2; hb.y=h3;
        __nv_bfloat162 la; la.x=l0; la.y=l1;
        __nv_bfloat162 lb; lb.x=l2; lb.y=l3;
        ((__nv_bfloat162*)g_xh)[i*2]   = ha;
        ((__nv_bfloat162*)g_xh)[i*2+1] = hb;
        ((__nv_bfloat162*)g_xl)[i*2]   = la;
        ((__nv_bfloat162*)g_xl)[i*2+1] = lb;
    }
}

// ------------- K1c: split + transpose W -------------
__global__ void split_wt(const float* __restrict__ W){
    int i = blockIdx.x*256 + threadIdx.x;
    if(i < CIN*MIDD){
        int c = i >> 8, m = i & 255;
        float v = W[i];                 // W[c][m], coalesced read
        __nv_bfloat16 h, l;
        bsplit(v, h, l);
        g_wth[m*CIN + c] = h;
        g_wtl[m*CIN + c] = l;
    }
}

// ------------- K2a: down-projection via mma, fused bias+norm+split ------------
// Tile 64x256 (full MID row per CTA), 8 warps (2x4), warp tile 32x64, K=768,
// 3 bf16-split passes -> 72 chunks of BK=32, 4-stage cp.async pipeline.
#define DPSTG 25600   // per-stage bytes: A 64*80 + B 256*80
__global__ __launch_bounds__(256) void dp_mma(const float* __restrict__ bias){
    extern __shared__ char smem[];
    __shared__ float bsh[MIDD];
    __shared__ float spart[64][4];
    __shared__ float rnorm[64];
    int t = threadIdx.x, lane = t & 31, w = t >> 5;
    int rowBase = blockIdx.x * 64;
    int wm = (w & 1) * 32, wn = (w >> 1) * 64;
    bsh[t] = bias[t];

    const __nv_bfloat16* Asrc[3] = {g_xh, g_xh, g_xl};
    const __nv_bfloat16* Bsrc[3] = {g_wth, g_wtl, g_wth};

    int ar = t >> 2, au = t & 3;      // cp.async: row, 16B-unit
    uint32_t sbase = smem_u32(smem);

    // ldmatrix lane offsets (same pattern as main gemm)
    int arow = wm + ((lane >> 3) & 1) * 8 + (lane & 7);
    int acol = (lane >> 4) * 8;
    uint32_t aoff = arow*ROWB + acol*2;
    int brow = wn + (lane >> 4) * 8 + (lane & 7);
    int bcol = ((lane >> 3) & 1) * 8;
    uint32_t boff = brow*ROWB + bcol*2;

    float acc[2][8][4];
    #pragma unroll
    for(int i=0;i<2;i++)
        #pragma unroll
        for(int j=0;j<8;j++)
            #pragma unroll
            for(int q=0;q<4;q++) acc[i][j][q] = 0.f;

    auto issue = [&](int c, int buf){
        int p = c / 24;
        int ko = (c % 24) * 32;
        const __nv_bfloat16* As = Asrc[p] + (size_t)(rowBase + ar)*CIN + ko + au*8;
        cpa16(sbase + buf*DPSTG + ar*ROWB + au*16, As);
        const __nv_bfloat16* B0 = Bsrc[p];
        #pragma unroll
        for(int it=0; it<4; it++){
            int r = ar + it*64;
            cpa16(sbase + buf*DPSTG + 5120 + r*ROWB + au*16,
                  B0 + (size_t)r*CIN + ko + au*8);
        }
        cp_commit();
    };

    issue(0,0); issue(1,1); issue(2,2);
    for(int c=0; c<72; c++){
        if(c < 70) cp_wait<2>();
        else if(c == 70) cp_wait<1>();
        else cp_wait<0>();
        __syncthreads();
        if(c+3 < 72) issue(c+3, (c+3)&3);
        int buf = c & 3;
        uint32_t bA = sbase + buf*DPSTG + aoff;
        uint32_t bB = sbase + buf*DPSTG + 5120 + boff;
        #pragma unroll
        for(int s=0;s<2;s++){
            uint32_t Af[2][4];
            #pragma unroll
            for(int i=0;i<2;i++) LDSM4(Af[i], bA + i*(16*ROWB) + s*32);
            uint32_t Bf[4][4];
            #pragma unroll
            for(int jp=0;jp<4;jp++) LDSM4(Bf[jp], bB + jp*(16*ROWB) + s*32);
            #pragma unroll
            for(int i=0;i<2;i++)
                #pragma unroll
                for(int j=0;j<8;j++)
                    MMA16816(acc[i][j], Af[i], Bf[j>>1][(j&1)*2], Bf[j>>1][(j&1)*2+1]);
        }
    }
    __syncthreads();

    // add bias
    #pragma unroll
    for(int i=0;i<2;i++)
        #pragma unroll
        for(int j=0;j<8;j++){
            int col = wn + j*8 + (lane & 3)*2;
            acc[i][j][0] += bsh[col];   acc[i][j][1] += bsh[col+1];
            acc[i][j][2] += bsh[col];   acc[i][j][3] += bsh[col+1];
        }
    // per-row sum of squares
    #pragma unroll
    for(int i=0;i<2;i++)
        #pragma unroll
        for(int h=0;h<2;h++){
            float s = 0.f;
            #pragma unroll
            for(int j=0;j<8;j++){
                float v0 = acc[i][j][h*2], v1 = acc[i][j][h*2+1];
                s += v0*v0 + v1*v1;
            }
            s += __shfl_xor_sync(0xFFFFFFFFu, s, 1);
            s += __shfl_xor_sync(0xFFFFFFFFu, s, 2);
            if((lane & 3) == 0)
                spart[wm + i*16 + h*8 + (lane>>2)][w>>1] = s;
        }
    __syncthreads();
    if(t < 64){
        float ss = spart[t][0] + spart[t][1] + spart[t][2] + spart[t][3];
        rnorm[t] = 1.f / fmaxf(sqrtf(ss), 1e-12f);
    }
    __syncthreads();
    // normalize + bf16 split + write
    #pragma unroll
    for(int i=0;i<2;i++)
        #pragma unroll
        for(int h=0;h<2;h++){
            int rl = wm + i*16 + h*8 + (lane>>2);
            float rs = rnorm[rl];
            size_t row = rowBase + rl;
            #pragma unroll
            for(int j=0;j<8;j++){
                int col = wn + j*8 + (lane & 3)*2;
                float v0 = acc[i][j][h*2] * rs, v1 = acc[i][j][h*2+1] * rs;
                __nv_bfloat16 h0,l0,h1,l1;
                bsplit(v0,h0,l0); bsplit(v1,h1,l1);
                __nv_bfloat162 hv; hv.x=h0; hv.y=h1;
                __nv_bfloat162 lv; lv.x=l0; lv.y=l1;
                *(__nv_bfloat162*)&g_znh[row*MIDD + col] = hv;
                *(__nv_bfloat162*)&g_znl[row*MIDD + col] = lv;
            }
        }
}

// ------------- K2: main GEMM, 4-stage pipeline, 1 sync/chunk ------------------
#define MSTG 20480    // per-stage bytes: A 128*80, B 128*80
__global__ __launch_bounds__(256) void gemm_mma(float* __restrict__ Cc){
    extern __shared__ char smem[];
    int t = threadIdx.x;
    int lane = t & 31, w = t >> 5;
    int rowBase = blockIdx.y * 128;
    int colBase = blockIdx.x * 128;

    const __nv_bfloat16* Asrc[3] = {g_znh, g_znh, g_znl};
    const __nv_bfloat16* Bsrc[3] = {g_enh, g_enl, g_enh};

    int ldr = t >> 1;
    int ldq = (t & 1) * 2;
    uint32_t sbase = smem_u32(smem);

    int wm = (w & 1) * 64, wn = (w >> 1) * 32;
    int arow = wm + ((lane >> 3) & 1) * 8 + (lane & 7);
    int acol = (lane >> 4) * 8;
    uint32_t aoff = arow*ROWB + acol*2;
    int brow = wn + (lane >> 4) * 8 + (lane & 7);
    int bcol = ((lane >> 3) & 1) * 8;
    uint32_t boff = brow*ROWB + bcol*2;

    float acc[4][4][4];
    #pragma unroll
    for(int i=0;i<4;i++)
        #pragma unroll
        for(int j=0;j<4;j++)
            #pragma unroll
            for(int q=0;q<4;q++) acc[i][j][q] = 0.f;

    auto issue = [&](int c, int buf){
        int p = c >> 3;
        int ko = (c & 7) * 32;
        const __nv_bfloat16* As = Asrc[p] + (size_t)(rowBase + ldr)*MIDD + ko + ldq*8;
        const __nv_bfloat16* Bs = Bsrc[p] + (size_t)(colBase + ldr)*MIDD + ko + ldq*8;
        uint32_t sa = sbase + buf*MSTG + ldr*ROWB + ldq*16;
        uint32_t sb = sa + 10240;
        cpa16(sa,      As);
        cpa16(sa + 16, As + 8);
        cpa16(sb,      Bs);
        cpa16(sb + 16, Bs + 8);
        cp_commit();
    };

    issue(0,0); issue(1,1); issue(2,2);
    for(int c=0; c<24; c++){
        if(c < 22) cp_wait<2>();
        else if(c == 22) cp_wait<1>();
        else cp_wait<0>();
        __syncthreads();
        if(c+3 < 24) issue(c+3, (c+3)&3);
        int buf = c & 3;
        uint32_t bA = sbase + buf*MSTG + aoff;
        uint32_t bB = sbase + buf*MSTG + 10240 + boff;
        #pragma unroll
        for(int s=0;s<2;s++){
            uint32_t Af[4][4];
            #pragma unroll
            for(int i=0;i<4;i++) LDSM4(Af[i], bA + i*(16*ROWB) + s*32);
            uint32_t Bf[2][4];
            #pragma unroll
            for(int jp=0;jp<2;jp++) LDSM4(Bf[jp], bB + jp*(16*ROWB) + s*32);
            #pragma unroll
            for(int i=0;i<4;i++)
                #pragma unroll
                for(int j=0;j<4;j++)
                    MMA16816(acc[i][j], Af[i], Bf[j>>1][(j&1)*2], Bf[j>>1][(j&1)*2+1]);
        }
    }

    // epilogue: store dots + fused per-row argmax
    #pragma unroll
    for(int i=0;i<4;i++){
        int r0 = rowBase + wm + i*16 + (lane >> 2);
        #pragma unroll
        for(int h=0;h<2;h++){
            int row = r0 + h*8;
            bool rok = row < NTOT;
            float best = -3.0e38f; int bcolv = 0;
            float* crow = Cc + (size_t)row * KTOT;
            #pragma unroll
            for(int j=0;j<4;j++){
                int col = colBase + wn + j*8 + (lane & 3)*2;
                float v0 = acc[i][j][h*2+0];
                float v1 = acc[i][j][h*2+1];
                if(rok && col < KTOT){
                    float2 v2 = {v0, v1};
                    *(float2*)(crow + col) = v2;
                    if(v0 > best){ best = v0; bcolv = col; }
                    if(v1 > best){ best = v1; bcolv = col+1; }
                }
            }
            unsigned long long key = rok
                ? (((unsigned long long)fsort(best)) << 32) |
                  (unsigned long long)(0xFFFFFFFFu - (unsigned)bcolv)
                : 0ull;
            {
                unsigned long long o1 = __shfl_xor_sync(0xFFFFFFFFu, key, 1);
                if(o1 > key) key = o1;
                unsigned long long o2 = __shfl_xor_sync(0xFFFFFFFFu, key, 2);
                if(o2 > key) key = o2;
            }
            if((lane & 3) == 0 && rok) atomicMax(&g_rowkey[row], key);
        }
    }
}

// ------------- K3: per-row softmax stats (exp^7 trick, float4) ----------------
__global__ void row_stats(const float* __restrict__ Cc){
    int n = blockIdx.x, t = threadIdx.x;
    unsigned long long key = g_rowkey[n];
    unsigned u = (unsigned)(key >> 32);
    unsigned ub = (u & 0x80000000u) ? (u ^ 0x80000000u) : ~u;
    float md = __uint_as_float(ub);
    int idx = (int)(0xFFFFFFFFu - (unsigned)(key & 0xFFFFFFFFull));

    const float4* row = (const float4*)(Cc + (size_t)n * KTOT);
    float st = 0.f, se = 0.f, te = 0.f;
    for(int k=t; k<KV4; k+=256){
        float4 v = row[k];
        #pragma unroll
        for(int q=0;q<4;q++){
            float d = (q==0)?v.x:(q==1)?v.y:(q==2)?v.z:v.w;
            float g = d - md;
            float eT = __expf(CT * g);
            st += eT;
            float e2 = eT*eT, e4 = e2*e2;
            float eE = e4*e2*eT;          // exp(CE*g) since CE = 7*CT
            se += eE;
            te += eE * (CE * g);
        }
    }
    st = warpReduceSum(st); se = warpReduceSum(se); te = warpReduceSum(te);
    __shared__ float r0[8], r1[8], r2[8];
    if((t & 31) == 0){ r0[t>>5]=st; r1[t>>5]=se; r2[t>>5]=te; }
    __syncthreads();
    if(t == 0){
        float a=0.f, b=0.f, c=0.f;
        #pragma unroll
        for(int i=0;i<8;i++){ a+=r0[i]; b+=r1[i]; c+=r2[i]; }
        g_invSt[n] = 1.f / a;
        g_invSe[n] = 1.f / b;
        g_maxdot[n] = md;
        g_idx[n] = idx;
        g_occ[idx] = 1;
        atomicAdd(&g_acc[0], 2.f - 2.f*md);
        atomicAdd(&g_acc[1], c/b - logf(b));
    }
}

// ------------- K4: probs + entropy column sums (exp^7, float4) ----------------
__global__ void probs_avg(float* __restrict__ Cc){
    int k4 = blockIdx.x*256 + threadIdx.x;
    bool ok = k4 < KV4;
    int n0 = blockIdx.y * 200;
    float a0=0.f, a1=0.f, a2=0.f, a3=0.f;
    if(ok){
        float4* C4 = (float4*)Cc;
        for(int n=n0; n<n0+200; n++){
            float md  = g_maxdot[n];
            float ist = g_invSt[n];
            float ise = g_invSe[n];
            size_t off = (size_t)n * KV4 + k4;
            float4 v = C4[off];
            float4 o;
            {
                float g = v.x - md; float eT = __expf(CT*g);
                o.x = eT*ist; float e2=eT*eT, e4=e2*e2; a0 += e4*e2*eT*ise;
            }
            {
                float g = v.y - md; float eT = __expf(CT*g);
                o.y = eT*ist; float e2=eT*eT, e4=e2*e2; a1 += e4*e2*eT*ise;
            }
            {
                float g = v.z - md; float eT = __expf(CT*g);
                o.z = eT*ist; float e2=eT*eT, e4=e2*e2; a2 += e4*e2*eT*ise;
            }
            {
                float g = v.w - md; float eT = __expf(CT*g);
                o.w = eT*ist; float e2=eT*eT, e4=e2*e2; a3 += e4*e2*eT*ise;
            }
            C4[off] = o;
        }
        int k = k4*4;
        atomicAdd(&g_avgp[k+0], a0);
        atomicAdd(&g_avgp[k+1], a1);
        atomicAdd(&g_avgp[k+2], a2);
        atomicAdd(&g_avgp[k+3], a3);
    }
}

// ------------- K5: scalars -------------
__global__ void finalize(float* __restrict__ scal){
    int t = threadIdx.x;
    float cnt = 0.f, s = 0.f;
    for(int k=t; k<KTOT; k+=256){
        cnt += g_occ[k] ? 1.f : 0.f;
        float ap = g_avgp[k] * (1.f/7200.f);
        s += ap * logf(ap + 1e-5f);
    }
    cnt = warpReduceSum(cnt); s = warpReduceSum(s);
    __shared__ float r0[8], r1[8];
    if((t & 31) == 0){ r0[t>>5]=cnt; r1[t>>5]=s; }
    __syncthreads();
    if(t == 0){
        float c=0.f, sl=0.f;
        #pragma unroll
        for(int i=0;i<8;i++){ c+=r0[i]; sl+=r1[i]; }
        float usage = c / (float)KTOT;
        float vq = g_acc[0] / (7200.f * 256.f);
        float sample_entropy = -(g_acc[1] / 7200.f);
        scal[0] = usage;
        scal[1] = vq;
        scal[2] = vq;
        scal[3] = sample_entropy + sl;
    }
}

// ------------- K6: gather z_q_ste -------------
__global__ void gather_zq(float* __restrict__ outz){
    int n = blockIdx.x, m = threadIdx.x;
    outz[(size_t)n*MIDD + m] = g_en[(size_t)g_idx[n]*MIDD + m];
}

// ------------- launch -------------
extern "C" void kernel_launch(void* const* d_in, const int* in_sizes, int n_in,
                              void* d_out, int out_size){
    const float* x   = (const float*)d_in[0];
    const float* W   = (const float*)d_in[1];
    const float* b   = (const float*)d_in[2];
    const float* emb = (const float*)d_in[3];
    float* out = (float*)d_out;
    float* zq = out;
    float* probs = out + (size_t)NTOT*MIDD;
    float* scal  = out + (size_t)NTOT*MIDD + (size_t)NTOT*KTOT;

    cudaFuncSetAttribute(gemm_mma, cudaFuncAttributeMaxDynamicSharedMemorySize, 4*MSTG);
    cudaFuncSetAttribute(dp_mma,   cudaFuncAttributeMaxDynamicSharedMemorySize, 4*DPSTG);

    init_k<<<(KTOT+255)/256, 256>>>();
    norm_emb<<<KTOT, 256>>>(emb);
    split_x<<<(NTOT*CIN/4 + 255)/256, 256>>>(x);
    split_wt<<<(CIN*MIDD + 255)/256, 256>>>(W);
    dp_mma<<<NPAD/64, 256, 4*DPSTG>>>(b);
    gemm_mma<<<dim3(KPAD/128, NPAD/128), 256, 4*MSTG>>>(probs);
    row_stats<<<NTOT, 256>>>(probs);
    probs_avg<<<dim3((KV4+255)/256, 36), 256>>>(probs);
    finalize<<<1, 256>>>(scal);
    gather_zq<<<NTOT, 256>>>(zq);
}

// round 5
// speedup vs baseline: 2.5416x; 1.1562x over previous
#include <cuda_runtime.h>
#include <cuda_bf16.h>
#include <cstdint>

#define NTOT 7200      // B*L
#define NPAD 7296      // 57 * 128  (also 114 * 64)
#define CIN  768
#define MIDD 256
#define KTOT 8912
#define KPAD 8960      // 70 * 128
#define KV4  2228      // KTOT/4
#define NSLOT 280      // 70 tiles * 4 warpN per row

#define CT (2.0f/0.07f)
#define CE (2.0f/0.01f)
#define ROWB 80        // dp kernel smem row stride
#define ROWB2 144      // main gemm smem row stride (64 bf16 + pad)
#define STG2 36864     // per-stage bytes main gemm
#define DPSTG 25600

// ------------- device scratch -------------
__device__ __nv_bfloat16 g_znh[NPAD*MIDD];
__device__ __nv_bfloat16 g_znl[NPAD*MIDD];
__device__ __nv_bfloat16 g_enh[KPAD*MIDD];
__device__ __nv_bfloat16 g_enl[KPAD*MIDD];
__device__ __nv_bfloat16 g_xh[NPAD*CIN];
__device__ __nv_bfloat16 g_xl[NPAD*CIN];
__device__ __nv_bfloat16 g_wth[MIDD*CIN];
__device__ __nv_bfloat16 g_wtl[MIDD*CIN];
__device__ float g_en[KTOT*MIDD];
__device__ float4 g_part[(size_t)NTOT*NSLOT];
__device__ unsigned long long g_rowkey[NTOT];
__device__ float g_maxdot[NTOT];
__device__ float g_invSt[NTOT];
__device__ float g_invSe[NTOT];
__device__ int   g_idx[NTOT];
__device__ int   g_occ[KTOT];
__device__ float g_avgp[KTOT];
__device__ float g_acc[4];

// ------------- helpers -------------
__device__ __forceinline__ float warpReduceSum(float v){
    #pragma unroll
    for(int o=16;o;o>>=1) v += __shfl_xor_sync(0xFFFFFFFFu, v, o);
    return v;
}
__device__ __forceinline__ unsigned fsort(float f){
    unsigned u = __float_as_uint(f);
    return u ^ ((u >> 31) ? 0xFFFFFFFFu : 0x80000000u);
}
__device__ __forceinline__ uint32_t smem_u32(const void* p){
    uint32_t a;
    asm("{ .reg .u64 t; cvta.to.shared.u64 t, %1; cvt.u32.u64 %0, t; }" : "=r"(a) : "l"(p));
    return a;
}
__device__ __forceinline__ void cpa16(uint32_t s, const void* g){
    asm volatile("cp.async.cg.shared.global [%0], [%1], 16;" :: "r"(s), "l"(g));
}
__device__ __forceinline__ void cp_commit(){
    asm volatile("cp.async.commit_group;");
}
template<int N> __device__ __forceinline__ void cp_wait(){
    asm volatile("cp.async.wait_group %0;" :: "n"(N));
}
__device__ __forceinline__ float pow7(float e){
    float e2 = e*e, e4 = e2*e2;
    return e4*e2*e;
}
#define LDSM4(R, ADDR) \
    asm volatile("ldmatrix.sync.aligned.m8n8.x4.shared.b16 {%0,%1,%2,%3}, [%4];" \
        : "=r"((R)[0]), "=r"((R)[1]), "=r"((R)[2]), "=r"((R)[3]) : "r"(ADDR))
#define MMA16816(D, A, B0, B1) \
    asm volatile("mma.sync.aligned.m16n8k16.row.col.f32.bf16.bf16.f32 " \
        "{%0,%1,%2,%3},{%4,%5,%6,%7},{%8,%9},{%0,%1,%2,%3};" \
        : "+f"((D)[0]), "+f"((D)[1]), "+f"((D)[2]), "+f"((D)[3]) \
        : "r"((A)[0]), "r"((A)[1]), "r"((A)[2]), "r"((A)[3]), "r"(B0), "r"(B1))

__device__ __forceinline__ void bsplit(float v, __nv_bfloat16& h, __nv_bfloat16& l){
    h = __float2bfloat16(v);
    l = __float2bfloat16(v - __bfloat162float(h));
}

// ------------- K0: init -------------
__global__ void init_k(){
    int i = blockIdx.x*256 + threadIdx.x;
    if(i < NTOT) g_rowkey[i] = 0ull;
    if(i < KTOT){ g_avgp[i] = 0.f; g_occ[i] = 0; }
    if(i < 4) g_acc[i] = 0.f;
}

// ------------- K1: normalize embedding + bf16 split -------------
__global__ void norm_emb(const float* __restrict__ emb){
    int k = blockIdx.x, m = threadIdx.x;
    float v = emb[k*MIDD + m];
    float s = warpReduceSum(v*v);
    __shared__ float sm[8];
    if((m & 31) == 0) sm[m>>5] = s;
    __syncthreads();
    if(m == 0){
        float t = 0.f;
        #pragma unroll
        for(int i=0;i<8;i++) t += sm[i];
        sm[0] = 1.f / fmaxf(sqrtf(t), 1e-12f);
    }
    __syncthreads();
    float nv = v * sm[0];
    g_en[k*MIDD + m] = nv;
    __nv_bfloat16 h, l;
    bsplit(nv, h, l);
    g_enh[k*MIDD + m] = h;
    g_enl[k*MIDD + m] = l;
}

// ------------- K1a: split x into bf16 hi/lo -------------
__global__ void split_x(const float* __restrict__ x){
    int i = blockIdx.x*256 + threadIdx.x;
    if(i < NTOT*CIN/4){
        float4 v = ((const float4*)x)[i];
        __nv_bfloat16 h0,l0,h1,l1,h2,l2,h3,l3;
        bsplit(v.x,h0,l0); bsplit(v.y,h1,l1); bsplit(v.z,h2,l2); bsplit(v.w,h3,l3);
        __nv_bfloat162 ha; ha.x=h0; ha.y=h1;
        __nv_bfloat162 hb; hb.x=h2; hb.y=h3;
        __nv_bfloat162 la; la.x=l0; la.y=l1;
        __nv_bfloat162 lb; lb.x=l2; lb.y=l3;
        ((__nv_bfloat162*)g_xh)[i*2]   = ha;
        ((__nv_bfloat162*)g_xh)[i*2+1] = hb;
        ((__nv_bfloat162*)g_xl)[i*2]   = la;
        ((__nv_bfloat162*)g_xl)[i*2+1] = lb;
    }
}

// ------------- K1c: split + transpose W -------------
__global__ void split_wt(const float* __restrict__ W){
    int i = blockIdx.x*256 + threadIdx.x;
    if(i < CIN*MIDD){
        int c = i >> 8, m = i & 255;
        float v = W[i];
        __nv_bfloat16 h, l;
        bsplit(v, h, l);
        g_wth[m*CIN + c] = h;
        g_wtl[m*CIN + c] = l;
    }
}

// ------------- K2a: down-projection via mma, fused bias+norm+split ------------
__global__ __launch_bounds__(256) void dp_mma(const float* __restrict__ bias){
    extern __shared__ char smem[];
    __shared__ float bsh[MIDD];
    __shared__ float spart[64][4];
    __shared__ float rnorm[64];
    int t = threadIdx.x, lane = t & 31, w = t >> 5;
    int rowBase = blockIdx.x * 64;
    int wm = (w & 1) * 32, wn = (w >> 1) * 64;
    bsh[t] = bias[t];

    const __nv_bfloat16* Asrc[3] = {g_xh, g_xh, g_xl};
    const __nv_bfloat16* Bsrc[3] = {g_wth, g_wtl, g_wth};

    int ar = t >> 2, au = t & 3;
    uint32_t sbase = smem_u32(smem);

    int arow = wm + ((lane >> 3) & 1) * 8 + (lane & 7);
    int acol = (lane >> 4) * 8;
    uint32_t aoff = arow*ROWB + acol*2;
    int brow = wn + (lane >> 4) * 8 + (lane & 7);
    int bcol = ((lane >> 3) & 1) * 8;
    uint32_t boff = brow*ROWB + bcol*2;

    float acc[2][8][4];
    #pragma unroll
    for(int i=0;i<2;i++)
        #pragma unroll
        for(int j=0;j<8;j++)
            #pragma unroll
            for(int q=0;q<4;q++) acc[i][j][q] = 0.f;

    auto issue = [&](int c, int buf){
        int p = c / 24;
        int ko = (c % 24) * 32;
        const __nv_bfloat16* As = Asrc[p] + (size_t)(rowBase + ar)*CIN + ko + au*8;
        cpa16(sbase + buf*DPSTG + ar*ROWB + au*16, As);
        const __nv_bfloat16* B0 = Bsrc[p];
        #pragma unroll
        for(int it=0; it<4; it++){
            int r = ar + it*64;
            cpa16(sbase + buf*DPSTG + 5120 + r*ROWB + au*16,
                  B0 + (size_t)r*CIN + ko + au*8);
        }
        cp_commit();
    };

    issue(0,0); issue(1,1); issue(2,2);
    for(int c=0; c<72; c++){
        if(c < 70) cp_wait<2>();
        else if(c == 70) cp_wait<1>();
        else cp_wait<0>();
        __syncthreads();
        if(c+3 < 72) issue(c+3, (c+3)&3);
        int buf = c & 3;
        uint32_t bA = sbase + buf*DPSTG + aoff;
        uint32_t bB = sbase + buf*DPSTG + 5120 + boff;
        #pragma unroll
        for(int s=0;s<2;s++){
            uint32_t Af[2][4];
            #pragma unroll
            for(int i=0;i<2;i++) LDSM4(Af[i], bA + i*(16*ROWB) + s*32);
            uint32_t Bf[4][4];
            #pragma unroll
            for(int jp=0;jp<4;jp++) LDSM4(Bf[jp], bB + jp*(16*ROWB) + s*32);
            #pragma unroll
            for(int i=0;i<2;i++)
                #pragma unroll
                for(int j=0;j<8;j++)
                    MMA16816(acc[i][j], Af[i], Bf[j>>1][(j&1)*2], Bf[j>>1][(j&1)*2+1]);
        }
    }
    __syncthreads();

    #pragma unroll
    for(int i=0;i<2;i++)
        #pragma unroll
        for(int j=0;j<8;j++){
            int col = wn + j*8 + (lane & 3)*2;
            acc[i][j][0] += bsh[col];   acc[i][j][1] += bsh[col+1];
            acc[i][j][2] += bsh[col];   acc[i][j][3] += bsh[col+1];
        }
    #pragma unroll
    for(int i=0;i<2;i++)
        #pragma unroll
        for(int h=0;h<2;h++){
            float s = 0.f;
            #pragma unroll
            for(int j=0;j<8;j++){
                float v0 = acc[i][j][h*2], v1 = acc[i][j][h*2+1];
                s += v0*v0 + v1*v1;
            }
            s += __shfl_xor_sync(0xFFFFFFFFu, s, 1);
            s += __shfl_xor_sync(0xFFFFFFFFu, s, 2);
            if((lane & 3) == 0)
                spart[wm + i*16 + h*8 + (lane>>2)][w>>1] = s;
        }
    __syncthreads();
    if(t < 64){
        float ss = spart[t][0] + spart[t][1] + spart[t][2] + spart[t][3];
        rnorm[t] = 1.f / fmaxf(sqrtf(ss), 1e-12f);
    }
    __syncthreads();
    #pragma unroll
    for(int i=0;i<2;i++)
        #pragma unroll
        for(int h=0;h<2;h++){
            int rl = wm + i*16 + h*8 + (lane>>2);
            float rs = rnorm[rl];
            size_t row = rowBase + rl;
            #pragma unroll
            for(int j=0;j<8;j++){
                int col = wn + j*8 + (lane & 3)*2;
                float v0 = acc[i][j][h*2] * rs, v1 = acc[i][j][h*2+1] * rs;
                __nv_bfloat16 h0,l0,h1,l1;
                bsplit(v0,h0,l0); bsplit(v1,h1,l1);
                __nv_bfloat162 hv; hv.x=h0; hv.y=h1;
                __nv_bfloat162 lv; lv.x=l0; lv.y=l1;
                *(__nv_bfloat162*)&g_znh[row*MIDD + col] = hv;
                *(__nv_bfloat162*)&g_znl[row*MIDD + col] = lv;
            }
        }
}

// ------------- K2: main GEMM, BK=64, 3-stage, fused softmax partials ----------
__global__ __launch_bounds__(256, 2) void gemm_mma(float* __restrict__ Cc){
    extern __shared__ char smem[];
    int t = threadIdx.x;
    int lane = t & 31, w = t >> 5;
    int rowBase = blockIdx.y * 128;
    int colBase = blockIdx.x * 128;

    const __nv_bfloat16* Asrc[3] = {g_znh, g_znh, g_znl};
    const __nv_bfloat16* Bsrc[3] = {g_enh, g_enl, g_enh};

    uint32_t sbase = smem_u32(smem);

    int wm = (w & 1) * 64, wn = (w >> 1) * 32;
    int arow = wm + ((lane >> 3) & 1) * 8 + (lane & 7);
    int acol = (lane >> 4) * 8;
    uint32_t aoff = arow*ROWB2 + acol*2;
    int brow = wn + (lane >> 4) * 8 + (lane & 7);
    int bcol = ((lane >> 3) & 1) * 8;
    uint32_t boff = brow*ROWB2 + bcol*2;

    float acc[4][4][4];
    #pragma unroll
    for(int i=0;i<4;i++)
        #pragma unroll
        for(int j=0;j<4;j++)
            #pragma unroll
            for(int q=0;q<4;q++) acc[i][j][q] = 0.f;

    auto issue = [&](int c, int stg){
        int p = c >> 2;
        int ko = (c & 3) * 64;
        uint32_t sa = sbase + stg*STG2;
        uint32_t sb = sa + 18432;
        const __nv_bfloat16* Ap = Asrc[p];
        const __nv_bfloat16* Bp = Bsrc[p];
        #pragma unroll
        for(int rep=0; rep<4; rep++){
            int la = t + rep*256;
            int r = la >> 3, u = la & 7;
            cpa16(sa + r*ROWB2 + u*16, Ap + (size_t)(rowBase + r)*MIDD + ko + u*8);
            cpa16(sb + r*ROWB2 + u*16, Bp + (size_t)(colBase + r)*MIDD + ko + u*8);
        }
        cp_commit();
    };

    issue(0,0); issue(1,1);
    for(int c=0; c<12; c++){
        if(c < 11) cp_wait<1>();
        else cp_wait<0>();
        __syncthreads();
        if(c+2 < 12) issue(c+2, (c+2)%3);
        int stg = c % 3;
        uint32_t bA = sbase + stg*STG2 + aoff;
        uint32_t bB = sbase + stg*STG2 + 18432 + boff;
        #pragma unroll
        for(int s=0;s<4;s++){
            uint32_t Af[4][4];
            #pragma unroll
            for(int i=0;i<4;i++) LDSM4(Af[i], bA + i*(16*ROWB2) + s*32);
            uint32_t Bf[2][4];
            #pragma unroll
            for(int jp=0;jp<2;jp++) LDSM4(Bf[jp], bB + jp*(16*ROWB2) + s*32);
            #pragma unroll
            for(int i=0;i<4;i++)
                #pragma unroll
                for(int j=0;j<4;j++)
                    MMA16816(acc[i][j], Af[i], Bf[j>>1][(j&1)*2], Bf[j>>1][(j&1)*2+1]);
        }
    }

    // epilogue: store dots + per-(row, warpN-slice) softmax partials + argmax
    #pragma unroll
    for(int i=0;i<4;i++){
        #pragma unroll
        for(int h=0;h<2;h++){
            int rl = wm + i*16 + h*8 + (lane >> 2);
            int row = rowBase + rl;
            bool rok = row < NTOT;
            float* crow = Cc + (size_t)row * KTOT;
            float v[8];
            float best = -1e30f; int bc = 0;
            #pragma unroll
            for(int j=0;j<4;j++){
                int col = colBase + wn + j*8 + (lane & 3)*2;
                float v0 = acc[i][j][h*2+0];
                float v1 = acc[i][j][h*2+1];
                bool cv = col < KTOT;
                if(rok && cv){
                    float2 p2; p2.x = v0; p2.y = v1;
                    *(float2*)(crow + col) = p2;
                    if(v0 > best){ best = v0; bc = col; }
                    if(v1 > best){ best = v1; bc = col+1; }
                }
                v[j*2]   = cv ? v0 : -1e4f;
                v[j*2+1] = cv ? v1 : -1e4f;
            }
            // local max over this lane's 8 + quad (4 lanes = 32 cols)
            float m = v[0];
            #pragma unroll
            for(int q=1;q<8;q++) m = fmaxf(m, v[q]);
            m = fmaxf(m, __shfl_xor_sync(0xFFFFFFFFu, m, 1));
            m = fmaxf(m, __shfl_xor_sync(0xFFFFFFFFu, m, 2));
            float st=0.f, se=0.f, te=0.f;
            #pragma unroll
            for(int q=0;q<8;q++){
                float g = CT * (v[q] - m);
                float eT = __expf(g);
                st += eT;
                float eE = pow7(eT);
                se += eE;
                te += eE * (7.f * g);
            }
            st += __shfl_xor_sync(0xFFFFFFFFu, st, 1);
            st += __shfl_xor_sync(0xFFFFFFFFu, st, 2);
            se += __shfl_xor_sync(0xFFFFFFFFu, se, 1);
            se += __shfl_xor_sync(0xFFFFFFFFu, se, 2);
            te += __shfl_xor_sync(0xFFFFFFFFu, te, 1);
            te += __shfl_xor_sync(0xFFFFFFFFu, te, 2);
            unsigned long long key =
                (((unsigned long long)fsort(best)) << 32) |
                (unsigned long long)(0xFFFFFFFFu - (unsigned)bc);
            {
                unsigned long long o1 = __shfl_xor_sync(0xFFFFFFFFu, key, 1);
                if(o1 > key) key = o1;
                unsigned long long o2 = __shfl_xor_sync(0xFFFFFFFFu, key, 2);
                if(o2 > key) key = o2;
            }
            if((lane & 3) == 0 && rok){
                float4 p4; p4.x = m; p4.y = st; p4.z = se; p4.w = te;
                g_part[(size_t)row*NSLOT + blockIdx.x*4 + (w>>1)] = p4;
                atomicMax(&g_rowkey[row], key);
            }
        }
    }
}

// ------------- K3: combine partials -> per-row stats (one warp per row) -------
__global__ void combine(){
    int t = threadIdx.x;
    int row = blockIdx.x*8 + (t>>5);
    int lane = t & 31;
    if(row >= NTOT) return;
    const float4* P = g_part + (size_t)row*NSLOT;
    float m = -1e30f, st = 0.f, se = 0.f, te = 0.f;
    for(int s=lane; s<NSLOT; s+=32){
        float4 p = P[s];
        float M = fmaxf(m, p.x);
        float ca = __expf(CT*(m - M));
        float cb = __expf(CT*(p.x - M));
        float ca7 = pow7(ca), cb7 = pow7(cb);
        st = st*ca + p.y*cb;
        te = (te + CE*(m - M)*se)*ca7 + (p.w + CE*(p.x - M)*p.z)*cb7;
        se = se*ca7 + p.z*cb7;
        m = M;
    }
    #pragma unroll
    for(int off=16; off; off>>=1){
        float om  = __shfl_xor_sync(0xFFFFFFFFu, m,  off);
        float ost = __shfl_xor_sync(0xFFFFFFFFu, st, off);
        float ose = __shfl_xor_sync(0xFFFFFFFFu, se, off);
        float ote = __shfl_xor_sync(0xFFFFFFFFu, te, off);
        float M = fmaxf(m, om);
        float ca = __expf(CT*(m - M));
        float cb = __expf(CT*(om - M));
        float ca7 = pow7(ca), cb7 = pow7(cb);
        st = st*ca + ost*cb;
        te = (te + CE*(m - M)*se)*ca7 + (ote + CE*(om - M)*ose)*cb7;
        se = se*ca7 + ose*cb7;
        m = M;
    }
    if(lane == 0){
        unsigned long long key = g_rowkey[row];
        int idx = (int)(0xFFFFFFFFu - (unsigned)(key & 0xFFFFFFFFull));
        g_maxdot[row] = m;
        g_invSt[row] = 1.f / st;
        g_invSe[row] = 1.f / se;
        g_idx[row] = idx;
        g_occ[idx] = 1;
        atomicAdd(&g_acc[0], 2.f - 2.f*m);
        atomicAdd(&g_acc[1], te/se - logf(se));
    }
}

// ------------- K4: probs + entropy column sums (exp^7, float4) ----------------
__global__ void probs_avg(float* __restrict__ Cc){
    int k4 = blockIdx.x*256 + threadIdx.x;
    bool ok = k4 < KV4;
    int n0 = blockIdx.y * 100;
    float a0=0.f, a1=0.f, a2=0.f, a3=0.f;
    if(ok){
        float4* C4 = (float4*)Cc;
        for(int n=n0; n<n0+100; n++){
            float md  = g_maxdot[n];
            float ist = g_invSt[n];
            float ise = g_invSe[n];
            size_t off = (size_t)n * KV4 + k4;
            float4 v = C4[off];
            float4 o;
            {
                float g = v.x - md; float eT = __expf(CT*g);
                o.x = eT*ist; a0 += pow7(eT)*ise;
            }
            {
                float g = v.y - md; float eT = __expf(CT*g);
                o.y = eT*ist; a1 += pow7(eT)*ise;
            }
            {
                float g = v.z - md; float eT = __expf(CT*g);
                o.z = eT*ist; a2 += pow7(eT)*ise;
            }
            {
                float g = v.w - md; float eT = __expf(CT*g);
                o.w = eT*ist; a3 += pow7(eT)*ise;
            }
            C4[off] = o;
        }
        int k = k4*4;
        atomicAdd(&g_avgp[k+0], a0);
        atomicAdd(&g_avgp[k+1], a1);
        atomicAdd(&g_avgp[k+2], a2);
        atomicAdd(&g_avgp[k+3], a3);
    }
}

// ------------- K5: scalars -------------
__global__ void finalize(float* __restrict__ scal){
    int t = threadIdx.x;
    float cnt = 0.f, s = 0.f;
    for(int k=t; k<KTOT; k+=256){
        cnt += g_occ[k] ? 1.f : 0.f;
        float ap = g_avgp[k] * (1.f/7200.f);
        s += ap * logf(ap + 1e-5f);
    }
    cnt = warpReduceSum(cnt); s = warpReduceSum(s);
    __shared__ float r0[8], r1[8];
    if((t & 31) == 0){ r0[t>>5]=cnt; r1[t>>5]=s; }
    __syncthreads();
    if(t == 0){
        float c=0.f, sl=0.f;
        #pragma unroll
        for(int i=0;i<8;i++){ c+=r0[i]; sl+=r1[i]; }
        float usage = c / (float)KTOT;
        float vq = g_acc[0] / (7200.f * 256.f);
        float sample_entropy = -(g_acc[1] / 7200.f);
        scal[0] = usage;
        scal[1] = vq;
        scal[2] = vq;
        scal[3] = sample_entropy + sl;
    }
}

// ------------- K6: gather z_q_ste -------------
__global__ void gather_zq(float* __restrict__ outz){
    int n = blockIdx.x, m = threadIdx.x;
    outz[(size_t)n*MIDD + m] = g_en[(size_t)g_idx[n]*MIDD + m];
}

// ------------- launch -------------
extern "C" void kernel_launch(void* const* d_in, const int* in_sizes, int n_in,
                              void* d_out, int out_size){
    const float* x   = (const float*)d_in[0];
    const float* W   = (const float*)d_in[1];
    const float* b   = (const float*)d_in[2];
    const float* emb = (const float*)d_in[3];
    float* out = (float*)d_out;
    float* zq = out;
    float* probs = out + (size_t)NTOT*MIDD;
    float* scal  = out + (size_t)NTOT*MIDD + (size_t)NTOT*KTOT;

    cudaFuncSetAttribute(gemm_mma, cudaFuncAttributeMaxDynamicSharedMemorySize, 3*STG2);
    cudaFuncSetAttribute(dp_mma,   cudaFuncAttributeMaxDynamicSharedMemorySize, 4*DPSTG);

    init_k<<<(KTOT+255)/256, 256>>>();
    norm_emb<<<KTOT, 256>>>(emb);
    split_x<<<(NTOT*CIN/4 + 255)/256, 256>>>(x);
    split_wt<<<(CIN*MIDD + 255)/256, 256>>>(W);
    dp_mma<<<NPAD/64, 256, 4*DPSTG>>>(b);
    gemm_mma<<<dim3(KPAD/128, NPAD/128), 256, 3*STG2>>>(probs);
    combine<<<NTOT/8, 256>>>();
    probs_avg<<<dim3((KV4+255)/256, 72), 256>>>(probs);
    finalize<<<1, 256>>>(scal);
    gather_zq<<<NTOT, 256>>>(zq);
}

// round 6
// speedup vs baseline: 2.5707x; 1.0115x over previous
#include <cuda_runtime.h>
#include <cuda_bf16.h>
#include <cstdint>

#define NTOT 7200      // B*L
#define NPAD 7296      // 57 * 128  (also 114 * 64)
#define CIN  768
#define MIDD 256
#define KTOT 8912
#define KPAD 8960      // 70 * 128
#define KV4  2228      // KTOT/4
#define NSLOT 280      // 70 tiles * 4 warpN slots per row

#define CT (2.0f/0.07f)
#define CE (2.0f/0.01f)
#define ROWB 80        // dp kernel smem row stride
#define ROWB2 144      // main gemm smem row stride (64 bf16 + pad)
#define STG2 36864     // per-stage bytes main gemm
#define DPSTG 25600

// ------------- device scratch -------------
__device__ __nv_bfloat16 g_znh[NPAD*MIDD];
__device__ __nv_bfloat16 g_znl[NPAD*MIDD];
__device__ __nv_bfloat16 g_enh[KPAD*MIDD];
__device__ __nv_bfloat16 g_enl[KPAD*MIDD];
__device__ __nv_bfloat16 g_xh[NPAD*CIN];
__device__ __nv_bfloat16 g_xl[NPAD*CIN];
__device__ __nv_bfloat16 g_wth[MIDD*CIN];
__device__ __nv_bfloat16 g_wtl[MIDD*CIN];
__device__ float g_en[KTOT*MIDD];
__device__ float4 g_part[(size_t)NTOT*NSLOT];
__device__ float g_fT[(size_t)NTOT*NSLOT];
__device__ float g_fE[(size_t)NTOT*NSLOT];
__device__ unsigned long long g_rowkey[NTOT];
__device__ int   g_idx[NTOT];
__device__ int   g_occ[KTOT];
__device__ float g_avgp[KTOT];
__device__ float g_acc[4];

// ------------- helpers -------------
__device__ __forceinline__ float warpReduceSum(float v){
    #pragma unroll
    for(int o=16;o;o>>=1) v += __shfl_xor_sync(0xFFFFFFFFu, v, o);
    return v;
}
__device__ __forceinline__ unsigned fsort(float f){
    unsigned u = __float_as_uint(f);
    return u ^ ((u >> 31) ? 0xFFFFFFFFu : 0x80000000u);
}
__device__ __forceinline__ uint32_t smem_u32(const void* p){
    uint32_t a;
    asm("{ .reg .u64 t; cvta.to.shared.u64 t, %1; cvt.u32.u64 %0, t; }" : "=r"(a) : "l"(p));
    return a;
}
__device__ __forceinline__ void cpa16(uint32_t s, const void* g){
    asm volatile("cp.async.cg.shared.global [%0], [%1], 16;" :: "r"(s), "l"(g));
}
__device__ __forceinline__ void cp_commit(){
    asm volatile("cp.async.commit_group;");
}
template<int N> __device__ __forceinline__ void cp_wait(){
    asm volatile("cp.async.wait_group %0;" :: "n"(N));
}
__device__ __forceinline__ float pow7(float e){
    float e2 = e*e, e4 = e2*e2;
    return e4*e2*e;
}
#define LDSM4(R, ADDR) \
    asm volatile("ldmatrix.sync.aligned.m8n8.x4.shared.b16 {%0,%1,%2,%3}, [%4];" \
        : "=r"((R)[0]), "=r"((R)[1]), "=r"((R)[2]), "=r"((R)[3]) : "r"(ADDR))
#define MMA16816(D, A, B0, B1) \
    asm volatile("mma.sync.aligned.m16n8k16.row.col.f32.bf16.bf16.f32 " \
        "{%0,%1,%2,%3},{%4,%5,%6,%7},{%8,%9},{%0,%1,%2,%3};" \
        : "+f"((D)[0]), "+f"((D)[1]), "+f"((D)[2]), "+f"((D)[3]) \
        : "r"((A)[0]), "r"((A)[1]), "r"((A)[2]), "r"((A)[3]), "r"(B0), "r"(B1))

__device__ __forceinline__ void bsplit(float v, __nv_bfloat16& h, __nv_bfloat16& l){
    h = __float2bfloat16(v);
    l = __float2bfloat16(v - __bfloat162float(h));
}

// ------------- K0: init -------------
__global__ void init_k(){
    int i = blockIdx.x*256 + threadIdx.x;
    if(i < NTOT) g_rowkey[i] = 0ull;
    if(i < KTOT){ g_avgp[i] = 0.f; g_occ[i] = 0; }
    if(i < 4) g_acc[i] = 0.f;
}

// ------------- K1: normalize embedding + bf16 split -------------
__global__ void norm_emb(const float* __restrict__ emb){
    int k = blockIdx.x, m = threadIdx.x;
    float v = emb[k*MIDD + m];
    float s = warpReduceSum(v*v);
    __shared__ float sm[8];
    if((m & 31) == 0) sm[m>>5] = s;
    __syncthreads();
    if(m == 0){
        float t = 0.f;
        #pragma unroll
        for(int i=0;i<8;i++) t += sm[i];
        sm[0] = 1.f / fmaxf(sqrtf(t), 1e-12f);
    }
    __syncthreads();
    float nv = v * sm[0];
    g_en[k*MIDD + m] = nv;
    __nv_bfloat16 h, l;
    bsplit(nv, h, l);
    g_enh[k*MIDD + m] = h;
    g_enl[k*MIDD + m] = l;
}

// ------------- K1a: split x into bf16 hi/lo -------------
__global__ void split_x(const float* __restrict__ x){
    int i = blockIdx.x*256 + threadIdx.x;
    if(i < NTOT*CIN/4){
        float4 v = ((const float4*)x)[i];
        __nv_bfloat16 h0,l0,h1,l1,h2,l2,h3,l3;
        bsplit(v.x,h0,l0); bsplit(v.y,h1,l1); bsplit(v.z,h2,l2); bsplit(v.w,h3,l3);
        __nv_bfloat162 ha; ha.x=h0; ha.y=h1;
        __nv_bfloat162 hb; hb.x=h2; hb.y=h3;
        __nv_bfloat162 la; la.x=l0; la.y=l1;
        __nv_bfloat162 lb; lb.x=l2; lb.y=l3;
        ((__nv_bfloat162*)g_xh)[i*2]   = ha;
        ((__nv_bfloat162*)g_xh)[i*2+1] = hb;
        ((__nv_bfloat162*)g_xl)[i*2]   = la;
        ((__nv_bfloat162*)g_xl)[i*2+1] = lb;
    }
}

// ------------- K1c: split + transpose W -------------
__global__ void split_wt(const float* __restrict__ W){
    int i = blockIdx.x*256 + threadIdx.x;
    if(i < CIN*MIDD){
        int c = i >> 8, m = i & 255;
        float v = W[i];
        __nv_bfloat16 h, l;
        bsplit(v, h, l);
        g_wth[m*CIN + c] = h;
        g_wtl[m*CIN + c] = l;
    }
}

// ------------- K2a: down-projection via mma, fused bias+norm+split ------------
__global__ __launch_bounds__(256) void dp_mma(const float* __restrict__ bias){
    extern __shared__ char smem[];
    __shared__ float bsh[MIDD];
    __shared__ float spart[64][4];
    __shared__ float rnorm[64];
    int t = threadIdx.x, lane = t & 31, w = t >> 5;
    int rowBase = blockIdx.x * 64;
    int wm = (w & 1) * 32, wn = (w >> 1) * 64;
    bsh[t] = bias[t];

    const __nv_bfloat16* Asrc[3] = {g_xh, g_xh, g_xl};
    const __nv_bfloat16* Bsrc[3] = {g_wth, g_wtl, g_wth};

    int ar = t >> 2, au = t & 3;
    uint32_t sbase = smem_u32(smem);

    int arow = wm + ((lane >> 3) & 1) * 8 + (lane & 7);
    int acol = (lane >> 4) * 8;
    uint32_t aoff = arow*ROWB + acol*2;
    int brow = wn + (lane >> 4) * 8 + (lane & 7);
    int bcol = ((lane >> 3) & 1) * 8;
    uint32_t boff = brow*ROWB + bcol*2;

    float acc[2][8][4];
    #pragma unroll
    for(int i=0;i<2;i++)
        #pragma unroll
        for(int j=0;j<8;j++)
            #pragma unroll
            for(int q=0;q<4;q++) acc[i][j][q] = 0.f;

    auto issue = [&](int c, int buf){
        int p = c / 24;
        int ko = (c % 24) * 32;
        const __nv_bfloat16* As = Asrc[p] + (size_t)(rowBase + ar)*CIN + ko + au*8;
        cpa16(sbase + buf*DPSTG + ar*ROWB + au*16, As);
        const __nv_bfloat16* B0 = Bsrc[p];
        #pragma unroll
        for(int it=0; it<4; it++){
            int r = ar + it*64;
            cpa16(sbase + buf*DPSTG + 5120 + r*ROWB + au*16,
                  B0 + (size_t)r*CIN + ko + au*8);
        }
        cp_commit();
    };

    issue(0,0); issue(1,1); issue(2,2);
    for(int c=0; c<72; c++){
        if(c < 70) cp_wait<2>();
        else if(c == 70) cp_wait<1>();
        else cp_wait<0>();
        __syncthreads();
        if(c+3 < 72) issue(c+3, (c+3)&3);
        int buf = c & 3;
        uint32_t bA = sbase + buf*DPSTG + aoff;
        uint32_t bB = sbase + buf*DPSTG + 5120 + boff;
        #pragma unroll
        for(int s=0;s<2;s++){
            uint32_t Af[2][4];
            #pragma unroll
            for(int i=0;i<2;i++) LDSM4(Af[i], bA + i*(16*ROWB) + s*32);
            uint32_t Bf[4][4];
            #pragma unroll
            for(int jp=0;jp<4;jp++) LDSM4(Bf[jp], bB + jp*(16*ROWB) + s*32);
            #pragma unroll
            for(int i=0;i<2;i++)
                #pragma unroll
                for(int j=0;j<8;j++)
                    MMA16816(acc[i][j], Af[i], Bf[j>>1][(j&1)*2], Bf[j>>1][(j&1)*2+1]);
        }
    }
    __syncthreads();

    #pragma unroll
    for(int i=0;i<2;i++)
        #pragma unroll
        for(int j=0;j<8;j++){
            int col = wn + j*8 + (lane & 3)*2;
            acc[i][j][0] += bsh[col];   acc[i][j][1] += bsh[col+1];
            acc[i][j][2] += bsh[col];   acc[i][j][3] += bsh[col+1];
        }
    #pragma unroll
    for(int i=0;i<2;i++)
        #pragma unroll
        for(int h=0;h<2;h++){
            float s = 0.f;
            #pragma unroll
            for(int j=0;j<8;j++){
                float v0 = acc[i][j][h*2], v1 = acc[i][j][h*2+1];
                s += v0*v0 + v1*v1;
            }
            s += __shfl_xor_sync(0xFFFFFFFFu, s, 1);
            s += __shfl_xor_sync(0xFFFFFFFFu, s, 2);
            if((lane & 3) == 0)
                spart[wm + i*16 + h*8 + (lane>>2)][w>>1] = s;
        }
    __syncthreads();
    if(t < 64){
        float ss = spart[t][0] + spart[t][1] + spart[t][2] + spart[t][3];
        rnorm[t] = 1.f / fmaxf(sqrtf(ss), 1e-12f);
    }
    __syncthreads();
    #pragma unroll
    for(int i=0;i<2;i++)
        #pragma unroll
        for(int h=0;h<2;h++){
            int rl = wm + i*16 + h*8 + (lane>>2);
            float rs = rnorm[rl];
            size_t row = rowBase + rl;
            #pragma unroll
            for(int j=0;j<8;j++){
                int col = wn + j*8 + (lane & 3)*2;
                float v0 = acc[i][j][h*2] * rs, v1 = acc[i][j][h*2+1] * rs;
                __nv_bfloat16 h0,l0,h1,l1;
                bsplit(v0,h0,l0); bsplit(v1,h1,l1);
                __nv_bfloat162 hv; hv.x=h0; hv.y=h1;
                __nv_bfloat162 lv; lv.x=l0; lv.y=l1;
                *(__nv_bfloat162*)&g_znh[row*MIDD + col] = hv;
                *(__nv_bfloat162*)&g_znl[row*MIDD + col] = lv;
            }
        }
}

// ------------- K2: main GEMM, stores eT = exp(CT*(dot - m_slot)) ---------------
__global__ __launch_bounds__(256, 2) void gemm_mma(float* __restrict__ Cc){
    extern __shared__ char smem[];
    int t = threadIdx.x;
    int lane = t & 31, w = t >> 5;
    int rowBase = blockIdx.y * 128;
    int colBase = blockIdx.x * 128;

    const __nv_bfloat16* Asrc[3] = {g_znh, g_znh, g_znl};
    const __nv_bfloat16* Bsrc[3] = {g_enh, g_enl, g_enh};

    uint32_t sbase = smem_u32(smem);

    int wm = (w & 1) * 64, wn = (w >> 1) * 32;
    int arow = wm + ((lane >> 3) & 1) * 8 + (lane & 7);
    int acol = (lane >> 4) * 8;
    uint32_t aoff = arow*ROWB2 + acol*2;
    int brow = wn + (lane >> 4) * 8 + (lane & 7);
    int bcol = ((lane >> 3) & 1) * 8;
    uint32_t boff = brow*ROWB2 + bcol*2;

    float acc[4][4][4];
    #pragma unroll
    for(int i=0;i<4;i++)
        #pragma unroll
        for(int j=0;j<4;j++)
            #pragma unroll
            for(int q=0;q<4;q++) acc[i][j][q] = 0.f;

    auto issue = [&](int c, int stg){
        int p = c >> 2;
        int ko = (c & 3) * 64;
        uint32_t sa = sbase + stg*STG2;
        uint32_t sb = sa + 18432;
        const __nv_bfloat16* Ap = Asrc[p];
        const __nv_bfloat16* Bp = Bsrc[p];
        #pragma unroll
        for(int rep=0; rep<4; rep++){
            int la = t + rep*256;
            int r = la >> 3, u = la & 7;
            cpa16(sa + r*ROWB2 + u*16, Ap + (size_t)(rowBase + r)*MIDD + ko + u*8);
            cpa16(sb + r*ROWB2 + u*16, Bp + (size_t)(colBase + r)*MIDD + ko + u*8);
        }
        cp_commit();
    };

    issue(0,0); issue(1,1);
    for(int c=0; c<12; c++){
        if(c < 11) cp_wait<1>();
        else cp_wait<0>();
        __syncthreads();
        if(c+2 < 12) issue(c+2, (c+2)%3);
        int stg = c % 3;
        uint32_t bA = sbase + stg*STG2 + aoff;
        uint32_t bB = sbase + stg*STG2 + 18432 + boff;
        #pragma unroll
        for(int s=0;s<4;s++){
            uint32_t Af[4][4];
            #pragma unroll
            for(int i=0;i<4;i++) LDSM4(Af[i], bA + i*(16*ROWB2) + s*32);
            uint32_t Bf[2][4];
            #pragma unroll
            for(int jp=0;jp<2;jp++) LDSM4(Bf[jp], bB + jp*(16*ROWB2) + s*32);
            #pragma unroll
            for(int i=0;i<4;i++)
                #pragma unroll
                for(int j=0;j<4;j++)
                    MMA16816(acc[i][j], Af[i], Bf[j>>1][(j&1)*2], Bf[j>>1][(j&1)*2+1]);
        }
    }

    // epilogue: slot max -> eT per element -> store eT + partials + argmax
    #pragma unroll
    for(int i=0;i<4;i++){
        #pragma unroll
        for(int h=0;h<2;h++){
            int rl = wm + i*16 + h*8 + (lane >> 2);
            int row = rowBase + rl;
            bool rok = row < NTOT;
            float* crow = Cc + (size_t)row * KTOT;
            float v[8];
            float best = -1e30f; int bc = 0;
            #pragma unroll
            for(int j=0;j<4;j++){
                int col = colBase + wn + j*8 + (lane & 3)*2;
                float v0 = acc[i][j][h*2+0];
                float v1 = acc[i][j][h*2+1];
                bool cv = col < KTOT;
                if(cv){
                    if(v0 > best){ best = v0; bc = col; }
                    if(v1 > best){ best = v1; bc = col+1; }
                }
                v[j*2]   = cv ? v0 : -1e4f;
                v[j*2+1] = cv ? v1 : -1e4f;
            }
            float m = v[0];
            #pragma unroll
            for(int q=1;q<8;q++) m = fmaxf(m, v[q]);
            m = fmaxf(m, __shfl_xor_sync(0xFFFFFFFFu, m, 1));
            m = fmaxf(m, __shfl_xor_sync(0xFFFFFFFFu, m, 2));
            float eTq[8];
            float st=0.f, se=0.f, te=0.f;
            #pragma unroll
            for(int q=0;q<8;q++){
                float g = CT * (v[q] - m);
                float eT = __expf(g);
                eTq[q] = eT;
                st += eT;
                float eE = pow7(eT);
                se += eE;
                te += eE * (7.f * g);
            }
            if(rok){
                #pragma unroll
                for(int j=0;j<4;j++){
                    int col = colBase + wn + j*8 + (lane & 3)*2;
                    if(col < KTOT){
                        float2 p2; p2.x = eTq[j*2]; p2.y = eTq[j*2+1];
                        *(float2*)(crow + col) = p2;
                    }
                }
            }
            st += __shfl_xor_sync(0xFFFFFFFFu, st, 1);
            st += __shfl_xor_sync(0xFFFFFFFFu, st, 2);
            se += __shfl_xor_sync(0xFFFFFFFFu, se, 1);
            se += __shfl_xor_sync(0xFFFFFFFFu, se, 2);
            te += __shfl_xor_sync(0xFFFFFFFFu, te, 1);
            te += __shfl_xor_sync(0xFFFFFFFFu, te, 2);
            unsigned long long key =
                (((unsigned long long)fsort(best)) << 32) |
                (unsigned long long)(0xFFFFFFFFu - (unsigned)bc);
            {
                unsigned long long o1 = __shfl_xor_sync(0xFFFFFFFFu, key, 1);
                if(o1 > key) key = o1;
                unsigned long long o2 = __shfl_xor_sync(0xFFFFFFFFu, key, 2);
                if(o2 > key) key = o2;
            }
            if((lane & 3) == 0 && rok){
                float4 p4; p4.x = m; p4.y = st; p4.z = se; p4.w = te;
                g_part[(size_t)row*NSLOT + blockIdx.x*4 + (w>>1)] = p4;
                atomicMax(&g_rowkey[row], key);
            }
        }
    }
}

// ------------- K3: combine partials + emit per-slot scale factors -------------
__global__ void combine(){
    int t = threadIdx.x;
    int row = blockIdx.x*8 + (t>>5);
    int lane = t & 31;
    if(row >= NTOT) return;
    const float4* P = g_part + (size_t)row*NSLOT;
    float m = -1e30f, st = 0.f, se = 0.f, te = 0.f;
    for(int s=lane; s<NSLOT; s+=32){
        float4 p = P[s];
        float M = fmaxf(m, p.x);
        float ca = __expf(CT*(m - M));
        float cb = __expf(CT*(p.x - M));
        float ca7 = pow7(ca), cb7 = pow7(cb);
        st = st*ca + p.y*cb;
        te = (te + CE*(m - M)*se)*ca7 + (p.w + CE*(p.x - M)*p.z)*cb7;
        se = se*ca7 + p.z*cb7;
        m = M;
    }
    #pragma unroll
    for(int off=16; off; off>>=1){
        float om  = __shfl_xor_sync(0xFFFFFFFFu, m,  off);
        float ost = __shfl_xor_sync(0xFFFFFFFFu, st, off);
        float ose = __shfl_xor_sync(0xFFFFFFFFu, se, off);
        float ote = __shfl_xor_sync(0xFFFFFFFFu, te, off);
        float M = fmaxf(m, om);
        float ca = __expf(CT*(m - M));
        float cb = __expf(CT*(om - M));
        float ca7 = pow7(ca), cb7 = pow7(cb);
        st = st*ca + ost*cb;
        te = (te + CE*(m - M)*se)*ca7 + (ote + CE*(om - M)*ose)*cb7;
        se = se*ca7 + ose*cb7;
        m = M;
    }
    // all lanes now hold final m/st/se/te
    float ist = 1.f / st, ise = 1.f / se;
    for(int s=lane; s<NSLOT; s+=32){
        float ms = P[s].x;
        float eT = __expf(CT*(ms - m));
        g_fT[(size_t)row*NSLOT + s] = eT * ist;
        g_fE[(size_t)row*NSLOT + s] = pow7(eT) * ise;
    }
    if(lane == 0){
        unsigned long long key = g_rowkey[row];
        int idx = (int)(0xFFFFFFFFu - (unsigned)(key & 0xFFFFFFFFull));
        g_idx[row] = idx;
        g_occ[idx] = 1;
        atomicAdd(&g_acc[0], 2.f - 2.f*m);
        atomicAdd(&g_acc[1], te/se - logf(se));
    }
}

// ------------- K4: probs + entropy column sums (no exp) -----------------------
__global__ void probs_avg(float* __restrict__ Cc){
    int k4 = blockIdx.x*256 + threadIdx.x;
    bool ok = k4 < KV4;
    int slot = k4 >> 3;
    int n0 = blockIdx.y * 100;
    float a0=0.f, a1=0.f, a2=0.f, a3=0.f;
    if(ok){
        float4* C4 = (float4*)Cc;
        for(int n=n0; n<n0+100; n++){
            float fT = g_fT[(size_t)n*NSLOT + slot];
            float fE = g_fE[(size_t)n*NSLOT + slot];
            size_t off = (size_t)n * KV4 + k4;
            float4 v = C4[off];
            float4 o;
            o.x = v.x * fT;  a0 += pow7(v.x) * fE;
            o.y = v.y * fT;  a1 += pow7(v.y) * fE;
            o.z = v.z * fT;  a2 += pow7(v.z) * fE;
            o.w = v.w * fT;  a3 += pow7(v.w) * fE;
            C4[off] = o;
        }
        int k = k4*4;
        atomicAdd(&g_avgp[k+0], a0);
        atomicAdd(&g_avgp[k+1], a1);
        atomicAdd(&g_avgp[k+2], a2);
        atomicAdd(&g_avgp[k+3], a3);
    }
}

// ------------- K5: scalars -------------
__global__ void finalize(float* __restrict__ scal){
    int t = threadIdx.x;
    float cnt = 0.f, s = 0.f;
    for(int k=t; k<KTOT; k+=256){
        cnt += g_occ[k] ? 1.f : 0.f;
        float ap = g_avgp[k] * (1.f/7200.f);
        s += ap * logf(ap + 1e-5f);
    }
    cnt = warpReduceSum(cnt); s = warpReduceSum(s);
    __shared__ float r0[8], r1[8];
    if((t & 31) == 0){ r0[t>>5]=cnt; r1[t>>5]=s; }
    __syncthreads();
    if(t == 0){
        float c=0.f, sl=0.f;
        #pragma unroll
        for(int i=0;i<8;i++){ c+=r0[i]; sl+=r1[i]; }
        float usage = c / (float)KTOT;
        float vq = g_acc[0] / (7200.f * 256.f);
        float sample_entropy = -(g_acc[1] / 7200.f);
        scal[0] = usage;
        scal[1] = vq;
        scal[2] = vq;
        scal[3] = sample_entropy + sl;
    }
}

// ------------- K6: gather z_q_ste -------------
__global__ void gather_zq(float* __restrict__ outz){
    int n = blockIdx.x, m = threadIdx.x;
    outz[(size_t)n*MIDD + m] = g_en[(size_t)g_idx[n]*MIDD + m];
}

// ------------- launch -------------
extern "C" void kernel_launch(void* const* d_in, const int* in_sizes, int n_in,
                              void* d_out, int out_size){
    const float* x   = (const float*)d_in[0];
    const float* W   = (const float*)d_in[1];
    const float* b   = (const float*)d_in[2];
    const float* emb = (const float*)d_in[3];
    float* out = (float*)d_out;
    float* zq = out;
    float* probs = out + (size_t)NTOT*MIDD;
    float* scal  = out + (size_t)NTOT*MIDD + (size_t)NTOT*KTOT;

    cudaFuncSetAttribute(gemm_mma, cudaFuncAttributeMaxDynamicSharedMemorySize, 3*STG2);
    cudaFuncSetAttribute(dp_mma,   cudaFuncAttributeMaxDynamicSharedMemorySize, 4*DPSTG);

    init_k<<<(KTOT+255)/256, 256>>>();
    norm_emb<<<KTOT, 256>>>(emb);
    split_x<<<(NTOT*CIN/4 + 255)/256, 256>>>(x);
    split_wt<<<(CIN*MIDD + 255)/256, 256>>>(W);
    dp_mma<<<NPAD/64, 256, 4*DPSTG>>>(b);
    gemm_mma<<<dim3(KPAD/128, NPAD/128), 256, 3*STG2>>>(probs);
    combine<<<NTOT/8, 256>>>();
    probs_avg<<<dim3((KV4+255)/256, 72), 256>>>(probs);
    finalize<<<1, 256>>>(scal);
    gather_zq<<<NTOT, 256>>>(zq);
}

// round 7
// speedup vs baseline: 2.5958x; 1.0098x over previous
#include <cuda_runtime.h>
#include <cuda_bf16.h>
#include <cuda_fp16.h>
#include <cstdint>

#define NTOT 7200      // B*L
#define NPAD 7296      // 57 * 128
#define CIN  768
#define MIDD 256
#define KTOT 8912
#define KPAD 8960      // 70 * 128
#define KV8  1114      // KTOT/8
#define NSLOT 280      // 70 tiles * 4 warpN slots per row

#define CT (2.0f/0.07f)
#define CE (2.0f/0.01f)
#define ROWB 80
#define ROWB2 144
#define STG2 36864
#define DPSTG 25600

// ------------- device scratch -------------
__device__ __nv_bfloat16 g_znh[NPAD*MIDD];
__device__ __nv_bfloat16 g_znl[NPAD*MIDD];
__device__ __nv_bfloat16 g_enh[KPAD*MIDD];
__device__ __nv_bfloat16 g_enl[KPAD*MIDD];
__device__ __nv_bfloat16 g_xh[NPAD*CIN];
__device__ __nv_bfloat16 g_xl[NPAD*CIN];
__device__ __nv_bfloat16 g_wth[MIDD*CIN];
__device__ __nv_bfloat16 g_wtl[MIDD*CIN];
__device__ float g_en[KTOT*MIDD];
__device__ __half g_eT[(size_t)NTOT*KTOT];
__device__ float4 g_part[(size_t)NTOT*NSLOT];
__device__ float g_fT[(size_t)NTOT*NSLOT];
__device__ float g_fE[(size_t)NTOT*NSLOT];
__device__ unsigned long long g_rowkey[NTOT];
__device__ int   g_idx[NTOT];
__device__ int   g_occ[KTOT];
__device__ float g_avgp[KTOT];
__device__ float g_acc[4];

// ------------- helpers -------------
__device__ __forceinline__ float warpReduceSum(float v){
    #pragma unroll
    for(int o=16;o;o>>=1) v += __shfl_xor_sync(0xFFFFFFFFu, v, o);
    return v;
}
__device__ __forceinline__ unsigned fsort(float f){
    unsigned u = __float_as_uint(f);
    return u ^ ((u >> 31) ? 0xFFFFFFFFu : 0x80000000u);
}
__device__ __forceinline__ uint32_t smem_u32(const void* p){
    uint32_t a;
    asm("{ .reg .u64 t; cvta.to.shared.u64 t, %1; cvt.u32.u64 %0, t; }" : "=r"(a) : "l"(p));
    return a;
}
__device__ __forceinline__ void cpa16(uint32_t s, const void* g){
    asm volatile("cp.async.cg.shared.global [%0], [%1], 16;" :: "r"(s), "l"(g));
}
__device__ __forceinline__ void cp_commit(){
    asm volatile("cp.async.commit_group;");
}
template<int N> __device__ __forceinline__ void cp_wait(){
    asm volatile("cp.async.wait_group %0;" :: "n"(N));
}
__device__ __forceinline__ float pow7(float e){
    float e2 = e*e, e4 = e2*e2;
    return e4*e2*e;
}
#define LDSM4(R, ADDR) \
    asm volatile("ldmatrix.sync.aligned.m8n8.x4.shared.b16 {%0,%1,%2,%3}, [%4];" \
        : "=r"((R)[0]), "=r"((R)[1]), "=r"((R)[2]), "=r"((R)[3]) : "r"(ADDR))
#define MMA16816(D, A, B0, B1) \
    asm volatile("mma.sync.aligned.m16n8k16.row.col.f32.bf16.bf16.f32 " \
        "{%0,%1,%2,%3},{%4,%5,%6,%7},{%8,%9},{%0,%1,%2,%3};" \
        : "+f"((D)[0]), "+f"((D)[1]), "+f"((D)[2]), "+f"((D)[3]) \
        : "r"((A)[0]), "r"((A)[1]), "r"((A)[2]), "r"((A)[3]), "r"(B0), "r"(B1))

__device__ __forceinline__ void bsplit(float v, __nv_bfloat16& h, __nv_bfloat16& l){
    h = __float2bfloat16(v);
    l = __float2bfloat16(v - __bfloat162float(h));
}

// ------------- K0: init -------------
__global__ void init_k(){
    int i = blockIdx.x*256 + threadIdx.x;
    if(i < NTOT) g_rowkey[i] = 0ull;
    if(i < KTOT){ g_avgp[i] = 0.f; g_occ[i] = 0; }
    if(i < 4) g_acc[i] = 0.f;
}

// ------------- K1: normalize embedding + bf16 split -------------
__global__ void norm_emb(const float* __restrict__ emb){
    int k = blockIdx.x, m = threadIdx.x;
    float v = emb[k*MIDD + m];
    float s = warpReduceSum(v*v);
    __shared__ float sm[8];
    if((m & 31) == 0) sm[m>>5] = s;
    __syncthreads();
    if(m == 0){
        float t = 0.f;
        #pragma unroll
        for(int i=0;i<8;i++) t += sm[i];
        sm[0] = 1.f / fmaxf(sqrtf(t), 1e-12f);
    }
    __syncthreads();
    float nv = v * sm[0];
    g_en[k*MIDD + m] = nv;
    __nv_bfloat16 h, l;
    bsplit(nv, h, l);
    g_enh[k*MIDD + m] = h;
    g_enl[k*MIDD + m] = l;
}

// ------------- K1a: split x into bf16 hi/lo -------------
__global__ void split_x(const float* __restrict__ x){
    int i = blockIdx.x*256 + threadIdx.x;
    if(i < NTOT*CIN/4){
        float4 v = ((const float4*)x)[i];
        __nv_bfloat16 h0,l0,h1,l1,h2,l2,h3,l3;
        bsplit(v.x,h0,l0); bsplit(v.y,h1,l1); bsplit(v.z,h2,l2); bsplit(v.w,h3,l3);
        __nv_bfloat162 ha; ha.x=h0; ha.y=h1;
        __nv_bfloat162 hb; hb.x=h2; hb.y=h3;
        __nv_bfloat162 la; la.x=l0; la.y=l1;
        __nv_bfloat162 lb; lb.x=l2; lb.y=l3;
        ((__nv_bfloat162*)g_xh)[i*2]   = ha;
        ((__nv_bfloat162*)g_xh)[i*2+1] = hb;
        ((__nv_bfloat162*)g_xl)[i*2]   = la;
        ((__nv_bfloat162*)g_xl)[i*2+1] = lb;
    }
}

// ------------- K1c: split + transpose W -------------
__global__ void split_wt(const float* __restrict__ W){
    int i = blockIdx.x*256 + threadIdx.x;
    if(i < CIN*MIDD){
        int c = i >> 8, m = i & 255;
        float v = W[i];
        __nv_bfloat16 h, l;
        bsplit(v, h, l);
        g_wth[m*CIN + c] = h;
        g_wtl[m*CIN + c] = l;
    }
}

// ------------- K2a: down-projection via mma, fused bias+norm+split ------------
__global__ __launch_bounds__(256) void dp_mma(const float* __restrict__ bias){
    extern __shared__ char smem[];
    __shared__ float bsh[MIDD];
    __shared__ float spart[64][4];
    __shared__ float rnorm[64];
    int t = threadIdx.x, lane = t & 31, w = t >> 5;
    int rowBase = blockIdx.x * 64;
    int wm = (w & 1) * 32, wn = (w >> 1) * 64;
    bsh[t] = bias[t];

    const __nv_bfloat16* Asrc[3] = {g_xh, g_xh, g_xl};
    const __nv_bfloat16* Bsrc[3] = {g_wth, g_wtl, g_wth};

    int ar = t >> 2, au = t & 3;
    uint32_t sbase = smem_u32(smem);

    int arow = wm + ((lane >> 3) & 1) * 8 + (lane & 7);
    int acol = (lane >> 4) * 8;
    uint32_t aoff = arow*ROWB + acol*2;
    int brow = wn + (lane >> 4) * 8 + (lane & 7);
    int bcol = ((lane >> 3) & 1) * 8;
    uint32_t boff = brow*ROWB + bcol*2;

    float acc[2][8][4];
    #pragma unroll
    for(int i=0;i<2;i++)
        #pragma unroll
        for(int j=0;j<8;j++)
            #pragma unroll
            for(int q=0;q<4;q++) acc[i][j][q] = 0.f;

    auto issue = [&](int c, int buf){
        int p = c / 24;
        int ko = (c % 24) * 32;
        const __nv_bfloat16* As = Asrc[p] + (size_t)(rowBase + ar)*CIN + ko + au*8;
        cpa16(sbase + buf*DPSTG + ar*ROWB + au*16, As);
        const __nv_bfloat16* B0 = Bsrc[p];
        #pragma unroll
        for(int it=0; it<4; it++){
            int r = ar + it*64;
            cpa16(sbase + buf*DPSTG + 5120 + r*ROWB + au*16,
                  B0 + (size_t)r*CIN + ko + au*8);
        }
        cp_commit();
    };

    issue(0,0); issue(1,1); issue(2,2);
    for(int c=0; c<72; c++){
        if(c < 70) cp_wait<2>();
        else if(c == 70) cp_wait<1>();
        else cp_wait<0>();
        __syncthreads();
        if(c+3 < 72) issue(c+3, (c+3)&3);
        int buf = c & 3;
        uint32_t bA = sbase + buf*DPSTG + aoff;
        uint32_t bB = sbase + buf*DPSTG + 5120 + boff;
        #pragma unroll
        for(int s=0;s<2;s++){
            uint32_t Af[2][4];
            #pragma unroll
            for(int i=0;i<2;i++) LDSM4(Af[i], bA + i*(16*ROWB) + s*32);
            uint32_t Bf[4][4];
            #pragma unroll
            for(int jp=0;jp<4;jp++) LDSM4(Bf[jp], bB + jp*(16*ROWB) + s*32);
            #pragma unroll
            for(int i=0;i<2;i++)
                #pragma unroll
                for(int j=0;j<8;j++)
                    MMA16816(acc[i][j], Af[i], Bf[j>>1][(j&1)*2], Bf[j>>1][(j&1)*2+1]);
        }
    }
    __syncthreads();

    #pragma unroll
    for(int i=0;i<2;i++)
        #pragma unroll
        for(int j=0;j<8;j++){
            int col = wn + j*8 + (lane & 3)*2;
            acc[i][j][0] += bsh[col];   acc[i][j][1] += bsh[col+1];
            acc[i][j][2] += bsh[col];   acc[i][j][3] += bsh[col+1];
        }
    #pragma unroll
    for(int i=0;i<2;i++)
        #pragma unroll
        for(int h=0;h<2;h++){
            float s = 0.f;
            #pragma unroll
            for(int j=0;j<8;j++){
                float v0 = acc[i][j][h*2], v1 = acc[i][j][h*2+1];
                s += v0*v0 + v1*v1;
            }
            s += __shfl_xor_sync(0xFFFFFFFFu, s, 1);
            s += __shfl_xor_sync(0xFFFFFFFFu, s, 2);
            if((lane & 3) == 0)
                spart[wm + i*16 + h*8 + (lane>>2)][w>>1] = s;
        }
    __syncthreads();
    if(t < 64){
        float ss = spart[t][0] + spart[t][1] + spart[t][2] + spart[t][3];
        rnorm[t] = 1.f / fmaxf(sqrtf(ss), 1e-12f);
    }
    __syncthreads();
    #pragma unroll
    for(int i=0;i<2;i++)
        #pragma unroll
        for(int h=0;h<2;h++){
            int rl = wm + i*16 + h*8 + (lane>>2);
            float rs = rnorm[rl];
            size_t row = rowBase + rl;
            #pragma unroll
            for(int j=0;j<8;j++){
                int col = wn + j*8 + (lane & 3)*2;
                float v0 = acc[i][j][h*2] * rs, v1 = acc[i][j][h*2+1] * rs;
                __nv_bfloat16 h0,l0,h1,l1;
                bsplit(v0,h0,l0); bsplit(v1,h1,l1);
                __nv_bfloat162 hv; hv.x=h0; hv.y=h1;
                __nv_bfloat162 lv; lv.x=l0; lv.y=l1;
                *(__nv_bfloat162*)&g_znh[row*MIDD + col] = hv;
                *(__nv_bfloat162*)&g_znl[row*MIDD + col] = lv;
            }
        }
}

// ------------- K2: main GEMM, stores eT (fp16) -------------------------------
__global__ __launch_bounds__(256, 2) void gemm_mma(){
    extern __shared__ char smem[];
    int t = threadIdx.x;
    int lane = t & 31, w = t >> 5;
    int rowBase = blockIdx.y * 128;
    int colBase = blockIdx.x * 128;

    const __nv_bfloat16* Asrc[3] = {g_znh, g_znh, g_znl};
    const __nv_bfloat16* Bsrc[3] = {g_enh, g_enl, g_enh};

    uint32_t sbase = smem_u32(smem);

    int wm = (w & 1) * 64, wn = (w >> 1) * 32;
    int arow = wm + ((lane >> 3) & 1) * 8 + (lane & 7);
    int acol = (lane >> 4) * 8;
    uint32_t aoff = arow*ROWB2 + acol*2;
    int brow = wn + (lane >> 4) * 8 + (lane & 7);
    int bcol = ((lane >> 3) & 1) * 8;
    uint32_t boff = brow*ROWB2 + bcol*2;

    float acc[4][4][4];
    #pragma unroll
    for(int i=0;i<4;i++)
        #pragma unroll
        for(int j=0;j<4;j++)
            #pragma unroll
            for(int q=0;q<4;q++) acc[i][j][q] = 0.f;

    auto issue = [&](int c, int stg){
        int p = c >> 2;
        int ko = (c & 3) * 64;
        uint32_t sa = sbase + stg*STG2;
        uint32_t sb = sa + 18432;
        const __nv_bfloat16* Ap = Asrc[p];
        const __nv_bfloat16* Bp = Bsrc[p];
        #pragma unroll
        for(int rep=0; rep<4; rep++){
            int la = t + rep*256;
            int r = la >> 3, u = la & 7;
            cpa16(sa + r*ROWB2 + u*16, Ap + (size_t)(rowBase + r)*MIDD + ko + u*8);
            cpa16(sb + r*ROWB2 + u*16, Bp + (size_t)(colBase + r)*MIDD + ko + u*8);
        }
        cp_commit();
    };

    issue(0,0); issue(1,1);
    for(int c=0; c<12; c++){
        if(c < 11) cp_wait<1>();
        else cp_wait<0>();
        __syncthreads();
        if(c+2 < 12) issue(c+2, (c+2)%3);
        int stg = c % 3;
        uint32_t bA = sbase + stg*STG2 + aoff;
        uint32_t bB = sbase + stg*STG2 + 18432 + boff;
        #pragma unroll
        for(int s=0;s<4;s++){
            uint32_t Af[4][4];
            #pragma unroll
            for(int i=0;i<4;i++) LDSM4(Af[i], bA + i*(16*ROWB2) + s*32);
            uint32_t Bf[2][4];
            #pragma unroll
            for(int jp=0;jp<2;jp++) LDSM4(Bf[jp], bB + jp*(16*ROWB2) + s*32);
            #pragma unroll
            for(int i=0;i<4;i++)
                #pragma unroll
                for(int j=0;j<4;j++)
                    MMA16816(acc[i][j], Af[i], Bf[j>>1][(j&1)*2], Bf[j>>1][(j&1)*2+1]);
        }
    }

    // epilogue: slot max -> eT per element -> store fp16 eT + partials + argmax
    #pragma unroll
    for(int i=0;i<4;i++){
        #pragma unroll
        for(int h=0;h<2;h++){
            int rl = wm + i*16 + h*8 + (lane >> 2);
            int row = rowBase + rl;
            bool rok = row < NTOT;
            float v[8];
            float best = -1e30f; int bc = 0;
            #pragma unroll
            for(int j=0;j<4;j++){
                int col = colBase + wn + j*8 + (lane & 3)*2;
                float v0 = acc[i][j][h*2+0];
                float v1 = acc[i][j][h*2+1];
                bool cv = col < KTOT;
                if(cv){
                    if(v0 > best){ best = v0; bc = col; }
                    if(v1 > best){ best = v1; bc = col+1; }
                }
                v[j*2]   = cv ? v0 : -1e4f;
                v[j*2+1] = cv ? v1 : -1e4f;
            }
            float m = v[0];
            #pragma unroll
            for(int q=1;q<8;q++) m = fmaxf(m, v[q]);
            m = fmaxf(m, __shfl_xor_sync(0xFFFFFFFFu, m, 1));
            m = fmaxf(m, __shfl_xor_sync(0xFFFFFFFFu, m, 2));
            float eTq[8];
            float st=0.f, se=0.f, te=0.f;
            #pragma unroll
            for(int q=0;q<8;q++){
                float g = CT * (v[q] - m);
                float eT = __expf(g);
                eTq[q] = eT;
                st += eT;
                float eE = pow7(eT);
                se += eE;
                te += eE * (7.f * g);
            }
            if(rok){
                __half* erow = g_eT + (size_t)row * KTOT;
                #pragma unroll
                for(int j=0;j<4;j++){
                    int col = colBase + wn + j*8 + (lane & 3)*2;
                    if(col < KTOT){
                        __half2 h2 = __floats2half2_rn(eTq[j*2], eTq[j*2+1]);
                        *(__half2*)(erow + col) = h2;
                    }
                }
            }
            st += __shfl_xor_sync(0xFFFFFFFFu, st, 1);
            st += __shfl_xor_sync(0xFFFFFFFFu, st, 2);
            se += __shfl_xor_sync(0xFFFFFFFFu, se, 1);
            se += __shfl_xor_sync(0xFFFFFFFFu, se, 2);
            te += __shfl_xor_sync(0xFFFFFFFFu, te, 1);
            te += __shfl_xor_sync(0xFFFFFFFFu, te, 2);
            unsigned long long key =
                (((unsigned long long)fsort(best)) << 32) |
                (unsigned long long)(0xFFFFFFFFu - (unsigned)bc);
            {
                unsigned long long o1 = __shfl_xor_sync(0xFFFFFFFFu, key, 1);
                if(o1 > key) key = o1;
                unsigned long long o2 = __shfl_xor_sync(0xFFFFFFFFu, key, 2);
                if(o2 > key) key = o2;
            }
            if((lane & 3) == 0 && rok){
                float4 p4; p4.x = m; p4.y = st; p4.z = se; p4.w = te;
                g_part[(size_t)row*NSLOT + blockIdx.x*4 + (w>>1)] = p4;
                atomicMax(&g_rowkey[row], key);
            }
        }
    }
}

// ------------- K3: combine partials + emit per-slot scale factors -------------
__global__ void combine(){
    int t = threadIdx.x;
    int row = blockIdx.x*8 + (t>>5);
    int lane = t & 31;
    if(row >= NTOT) return;
    const float4* P = g_part + (size_t)row*NSLOT;
    float m = -1e30f, st = 0.f, se = 0.f, te = 0.f;
    for(int s=lane; s<NSLOT; s+=32){
        float4 p = P[s];
        float M = fmaxf(m, p.x);
        float ca = __expf(CT*(m - M));
        float cb = __expf(CT*(p.x - M));
        float ca7 = pow7(ca), cb7 = pow7(cb);
        st = st*ca + p.y*cb;
        te = (te + CE*(m - M)*se)*ca7 + (p.w + CE*(p.x - M)*p.z)*cb7;
        se = se*ca7 + p.z*cb7;
        m = M;
    }
    #pragma unroll
    for(int off=16; off; off>>=1){
        float om  = __shfl_xor_sync(0xFFFFFFFFu, m,  off);
        float ost = __shfl_xor_sync(0xFFFFFFFFu, st, off);
        float ose = __shfl_xor_sync(0xFFFFFFFFu, se, off);
        float ote = __shfl_xor_sync(0xFFFFFFFFu, te, off);
        float M = fmaxf(m, om);
        float ca = __expf(CT*(m - M));
        float cb = __expf(CT*(om - M));
        float ca7 = pow7(ca), cb7 = pow7(cb);
        st = st*ca + ost*cb;
        te = (te + CE*(m - M)*se)*ca7 + (ote + CE*(om - M)*ose)*cb7;
        se = se*ca7 + ose*cb7;
        m = M;
    }
    float ist = 1.f / st, ise = 1.f / se;
    for(int s=lane; s<NSLOT; s+=32){
        float ms = P[s].x;
        float eT = __expf(CT*(ms - m));
        g_fT[(size_t)row*NSLOT + s] = eT * ist;
        g_fE[(size_t)row*NSLOT + s] = pow7(eT) * ise;
    }
    if(lane == 0){
        unsigned long long key = g_rowkey[row];
        int idx = (int)(0xFFFFFFFFu - (unsigned)(key & 0xFFFFFFFFull));
        g_idx[row] = idx;
        g_occ[idx] = 1;
        atomicAdd(&g_acc[0], 2.f - 2.f*m);
        atomicAdd(&g_acc[1], te/se - logf(se));
    }
}

// ------------- K4: probs + entropy column sums (fp16 eT in, f32 probs out) ----
__global__ void probs_avg(float* __restrict__ Cc){
    int k8 = blockIdx.x*256 + threadIdx.x;
    if(k8 >= KV8) return;
    int slot = k8 >> 2;              // 8 cols per k8, 32 cols per slot
    int n0 = blockIdx.y * 50;
    float a[8];
    #pragma unroll
    for(int q=0;q<8;q++) a[q] = 0.f;
    const uint4* E = (const uint4*)g_eT;
    for(int n=n0; n<n0+50; n++){
        float fT = g_fT[(size_t)n*NSLOT + slot];
        float fE = g_fE[(size_t)n*NSLOT + slot];
        uint4 ev = E[(size_t)n*KV8 + k8];
        float2 f0 = __half22float2(*(__half2*)&ev.x);
        float2 f1 = __half22float2(*(__half2*)&ev.y);
        float2 f2 = __half22float2(*(__half2*)&ev.z);
        float2 f3 = __half22float2(*(__half2*)&ev.w);
        float vv[8] = {f0.x,f0.y,f1.x,f1.y,f2.x,f2.y,f3.x,f3.y};
        float4 o0, o1;
        o0.x = vv[0]*fT; o0.y = vv[1]*fT; o0.z = vv[2]*fT; o0.w = vv[3]*fT;
        o1.x = vv[4]*fT; o1.y = vv[5]*fT; o1.z = vv[6]*fT; o1.w = vv[7]*fT;
        #pragma unroll
        for(int q=0;q<8;q++) a[q] += pow7(vv[q]) * fE;
        size_t off = (size_t)n * KTOT + (size_t)k8*8;
        *(float4*)(Cc + off)     = o0;
        *(float4*)(Cc + off + 4) = o1;
    }
    int k = k8*8;
    #pragma unroll
    for(int q=0;q<8;q++) atomicAdd(&g_avgp[k+q], a[q]);
}

// ------------- K5: scalars -------------
__global__ void finalize(float* __restrict__ scal){
    int t = threadIdx.x;
    float cnt = 0.f, s = 0.f;
    for(int k=t; k<KTOT; k+=256){
        cnt += g_occ[k] ? 1.f : 0.f;
        float ap = g_avgp[k] * (1.f/7200.f);
        s += ap * logf(ap + 1e-5f);
    }
    cnt = warpReduceSum(cnt); s = warpReduceSum(s);
    __shared__ float r0[8], r1[8];
    if((t & 31) == 0){ r0[t>>5]=cnt; r1[t>>5]=s; }
    __syncthreads();
    if(t == 0){
        float c=0.f, sl=0.f;
        #pragma unroll
        for(int i=0;i<8;i++){ c+=r0[i]; sl+=r1[i]; }
        float usage = c / (float)KTOT;
        float vq = g_acc[0] / (7200.f * 256.f);
        float sample_entropy = -(g_acc[1] / 7200.f);
        scal[0] = usage;
        scal[1] = vq;
        scal[2] = vq;
        scal[3] = sample_entropy + sl;
    }
}

// ------------- K6: gather z_q_ste -------------
__global__ void gather_zq(float* __restrict__ outz){
    int n = blockIdx.x, m = threadIdx.x;
    outz[(size_t)n*MIDD + m] = g_en[(size_t)g_idx[n]*MIDD + m];
}

// ------------- launch -------------
extern "C" void kernel_launch(void* const* d_in, const int* in_sizes, int n_in,
                              void* d_out, int out_size){
    const float* x   = (const float*)d_in[0];
    const float* W   = (const float*)d_in[1];
    const float* b   = (const float*)d_in[2];
    const float* emb = (const float*)d_in[3];
    float* out = (float*)d_out;
    float* zq = out;
    float* probs = out + (size_t)NTOT*MIDD;
    float* scal  = out + (size_t)NTOT*MIDD + (size_t)NTOT*KTOT;

    cudaFuncSetAttribute(gemm_mma, cudaFuncAttributeMaxDynamicSharedMemorySize, 3*STG2);
    cudaFuncSetAttribute(dp_mma,   cudaFuncAttributeMaxDynamicSharedMemorySize, 4*DPSTG);

    init_k<<<(KTOT+255)/256, 256>>>();
    norm_emb<<<KTOT, 256>>>(emb);
    split_x<<<(NTOT*CIN/4 + 255)/256, 256>>>(x);
    split_wt<<<(CIN*MIDD + 255)/256, 256>>>(W);
    dp_mma<<<NPAD/64, 256, 4*DPSTG>>>(b);
    gemm_mma<<<dim3(KPAD/128, NPAD/128), 256, 3*STG2>>>();
    combine<<<NTOT/8, 256>>>();
    probs_avg<<<dim3((KV8+255)/256, 144), 256>>>(probs);
    finalize<<<1, 256>>>(scal);
    gather_zq<<<NTOT, 256>>>(zq);
}